// round 6
// baseline (speedup 1.0000x reference)
#include <cuda_runtime.h>
#include <math.h>
#include <stdint.h>

#define HD 128
#define NN 256
#define NB 16

// Scratch (allocation-free rule: __device__ globals)
__device__ float g_h[NN][HD];    // layer-2 output (relu)
__device__ float g_P[32][HD];    // per-block partial sums of dinv*h (for scan)
__device__ float g_A0[NN][HD];   // h3 @ W1a + b1   (batch 0)
__device__ float g_B0[NN][HD];   // h3 @ W1b        (batch 0)
__device__ float g_pb[NB];       // constant edge prob per batch (b>=1)

// 32KB stage load via cp.async (8 x 16B per thread, 256 threads)
__device__ __forceinline__ void cp_stage(uint32_t dst, const float* src, int tid) {
    const char* s = (const char*)src + tid * 16;
    uint32_t d = dst + tid * 16;
#pragma unroll
    for (int i = 0; i < 8; i++)
        asm volatile("cp.async.cg.shared.global [%0], [%1], 16;"
                     :: "r"(d + i * 4096), "l"(s + i * 4096));
    asm volatile("cp.async.commit_group;" ::: "memory");
}
#define CP_WAIT1() asm volatile("cp.async.wait_group 1;" ::: "memory")
#define CP_WAIT0() asm volatile("cp.async.wait_group 0;" ::: "memory")

// ---------------------------------------------------------------------------
// K1: blocks 0..31  : batch-0 (emb -> u -> closed-form layer-1 + scan ->
//                     layer-2 GEMM), cp.async double-buffered weight stages.
//     blocks 32..46 : node-constant chains for b = 1..15 -> g_pb (11 stages).
// grid 47 x 256, dynamic smem 64KB (2 x 32KB stage buffers)
// ---------------------------------------------------------------------------
__global__ void k1(const float* __restrict__ z, const float* __restrict__ We,
                   const float* __restrict__ be, const float* __restrict__ Wg,
                   const float* __restrict__ bg, const float* __restrict__ W1a,
                   const float* __restrict__ W1b, const float* __restrict__ b1,
                   const float* __restrict__ W2, const float* __restrict__ b2) {
    extern __shared__ __align__(16) float buf[];   // 2 x 8192 floats
    __shared__ __align__(16) float gs[8][HD];
    __shared__ __align__(16) float hs[8][HD];
    __shared__ float zs[64];
    __shared__ float vv[HD];
    __shared__ float red[2][HD];
    __shared__ float ds[NN];
    __shared__ float wsum[8];
    int tid = threadIdx.x, bk = blockIdx.x;
    int d = tid & 127, hf = tid >> 7;
    int warp = tid >> 5, lane = tid & 31;
    uint32_t sb = (uint32_t)__cvta_generic_to_shared(buf);

    if (bk < 32) {
        // ---- batch-0 path: 5 stages ----
        const float* srcs[5] = { We, Wg, Wg + 64 * HD,
                                 Wg + HD * HD, Wg + HD * HD + 64 * HD };
        cp_stage(sb, srcs[0], tid);
        if (tid < 64) zs[tid] = z[tid];
        ds[tid] = rsqrtf((float)(tid + 1));
        float u = 0.f;
        float4 acc = make_float4(0.f, 0.f, 0.f, 0.f);
#pragma unroll
        for (int s = 0; s < 5; s++) {
            if (s + 1 < 5) { cp_stage(sb + ((s + 1) & 1) * 32768, srcs[s + 1], tid); CP_WAIT1(); }
            else CP_WAIT0();
            __syncthreads();
            const float* B = buf + (s & 1) * 8192;
            if (s == 0) {
                // embedding partial over this thread's k-half of We (32 k each)
                float p0 = 0.f, p1 = 0.f; int kb = hf * 32;
#pragma unroll 8
                for (int kk = 0; kk < 32; kk += 2) {
                    p0 = fmaf(zs[kb + kk],     B[(kb + kk) * HD + d],     p0);
                    p1 = fmaf(zs[kb + kk + 1], B[(kb + kk + 1) * HD + d], p1);
                }
                red[hf][d] = p0 + p1;
                __syncthreads();
                if (tid < 128) vv[d] = red[0][d] + red[1][d] + be[d];
            } else if (s <= 2) {
                // u partials over Wg0 halves
                int hh = s - 1;
                float p0 = 0.f, p1 = 0.f; int kb = hf * 32;
#pragma unroll 8
                for (int kk = 0; kk < 32; kk += 2) {
                    p0 = fmaf(vv[hh * 64 + kb + kk],     B[(kb + kk) * HD + d],     p0);
                    p1 = fmaf(vv[hh * 64 + kb + kk + 1], B[(kb + kk + 1) * HD + d], p1);
                }
                u += p0 + p1;
                if (s == 2) {
                    red[hf][d] = u;
                    __syncthreads();
                    if (tid < 128) {
                        // closed-form layer-1 + exclusive dinv-scan to this block
                        float uf = red[0][d] + red[1][d];
                        float bg0 = bg[d];
                        float c = 0.f, Dex = 0.f;
                        int base = bk * 8;
                        for (int j = 0; j < base + 8; j++) {
                            float dv = ds[j];
                            float sc = fmaf(dv, Dex, dv * dv);
                            float h1 = fmaxf(fmaf(sc, uf, bg0), 0.f);
                            if (j >= base) gs[j - base][d] = fmaf(dv, c, dv * dv * h1);
                            c = fmaf(dv, h1, c);
                            Dex += dv;
                        }
                    }
                }
            } else {
                // layer-2 GEMM half: warp-per-row, float4 columns
                if (s == 3) acc = ((const float4*)(bg + HD))[lane];
                const float4* Ws4 = (const float4*)B;
                int ko = (s - 3) * 64;
#pragma unroll 8
                for (int k = 0; k < 64; k++) {
                    float g = gs[warp][ko + k];
                    float4 w = Ws4[k * 32 + lane];
                    acc.x = fmaf(g, w.x, acc.x); acc.y = fmaf(g, w.y, acc.y);
                    acc.z = fmaf(g, w.z, acc.z); acc.w = fmaf(g, w.w, acc.w);
                }
            }
            __syncthreads();
        }
        acc.x = fmaxf(acc.x, 0.f); acc.y = fmaxf(acc.y, 0.f);
        acc.z = fmaxf(acc.z, 0.f); acc.w = fmaxf(acc.w, 0.f);
        int base = bk * 8;
        ((float4*)&g_h[base + warp][0])[lane] = acc;
        float dj = ds[base + warp];
        ((float4*)&hs[warp][0])[lane] = make_float4(acc.x * dj, acc.y * dj, acc.z * dj, acc.w * dj);
        __syncthreads();
        if (tid < HD) {
            float sum = 0.f;
#pragma unroll
            for (int w = 0; w < 8; w++) sum += hs[w][tid];
            g_P[bk][tid] = sum;
        }
    } else {
        // ---- node-constant chain for batch b = bk-31: 11 stages ----
        int b = bk - 31;
        const float* srcs[11] = { We,
            Wg,              Wg + 64 * HD,
            Wg + HD * HD,    Wg + HD * HD + 64 * HD,
            Wg + 2 * HD * HD, Wg + 2 * HD * HD + 64 * HD,
            W1a,             W1a + 64 * HD,
            W1b,             W1b + 64 * HD };
        cp_stage(sb, srcs[0], tid);
        if (tid < 64) zs[tid] = z[b * 64 + tid];
        float accL = 0.f, aA = 0.f, aB = 0.f, aAf = 0.f;
#pragma unroll
        for (int s = 0; s < 11; s++) {
            if (s + 1 < 11) { cp_stage(sb + ((s + 1) & 1) * 32768, srcs[s + 1], tid); CP_WAIT1(); }
            else CP_WAIT0();
            __syncthreads();
            const float* B = buf + (s & 1) * 8192;
            if (s == 0) {
                float p0 = 0.f, p1 = 0.f; int kb = hf * 32;
#pragma unroll 8
                for (int kk = 0; kk < 32; kk += 2) {
                    p0 = fmaf(zs[kb + kk],     B[(kb + kk) * HD + d],     p0);
                    p1 = fmaf(zs[kb + kk + 1], B[(kb + kk + 1) * HD + d], p1);
                }
                red[hf][d] = p0 + p1;
                __syncthreads();
                if (tid < 128) vv[d] = red[0][d] + red[1][d] + be[d];
            } else {
                int g = (s - 1) >> 1, hh = (s - 1) & 1;
                float p0 = 0.f, p1 = 0.f; int kb = hf * 32;
#pragma unroll 8
                for (int kk = 0; kk < 32; kk += 2) {
                    p0 = fmaf(vv[hh * 64 + kb + kk],     B[(kb + kk) * HD + d],     p0);
                    p1 = fmaf(vv[hh * 64 + kb + kk + 1], B[(kb + kk + 1) * HD + d], p1);
                }
                float pt = p0 + p1;
                if (s <= 6) accL += pt;
                else if (s <= 8) aA += pt;
                else aB += pt;
                if (hh == 1 && g < 3) {        // GCN layer boundary
                    red[hf][d] = accL;
                    __syncthreads();
                    if (tid < 128) vv[d] = fmaxf(red[0][d] + red[1][d] + bg[g * HD + d], 0.f);
                    accL = 0.f;
                }
                if (s == 8) {                  // W1a done
                    red[hf][d] = aA;
                    __syncthreads();
                    if (tid < 128) aAf = red[0][d] + red[1][d] + b1[d];
                }
            }
            __syncthreads();
        }
        red[hf][d] = aB;
        __syncthreads();
        float t = 0.f;
        if (tid < 128) t = fmaxf(aAf + red[0][d] + red[1][d], 0.f) * W2[d];
        for (int off = 16; off > 0; off >>= 1)
            t += __shfl_down_sync(0xffffffffu, t, off);
        if ((tid & 31) == 0) wsum[tid >> 5] = t;
        __syncthreads();
        if (tid == 0) {
            float ssum = wsum[0] + wsum[1] + wsum[2] + wsum[3]
                       + wsum[4] + wsum[5] + wsum[6] + wsum[7] + b2[0];
            g_pb[b] = 1.f / (1.f + __expf(-ssum));
        }
    }
}

// ---------------------------------------------------------------------------
// K2: block-prefix scan -> layer-3 GEMM+ReLU -> A0/B0 GEMMs, 6 cp.async
// stages double-buffered. grid 32 x 256, dynamic smem 64KB.
// ---------------------------------------------------------------------------
__global__ void k2(const float* __restrict__ Wg2, const float* __restrict__ bg2,
                   const float* __restrict__ W1a, const float* __restrict__ W1b,
                   const float* __restrict__ b1) {
    extern __shared__ __align__(16) float buf[];
    __shared__ __align__(16) float gs[8][HD];
    __shared__ __align__(16) float hs[8][HD];
    int tid = threadIdx.x, bk = blockIdx.x, base = bk * 8;
    int warp = tid >> 5, lane = tid & 31;
    uint32_t sb = (uint32_t)__cvta_generic_to_shared(buf);
    const float* srcs[6] = { Wg2, Wg2 + 64 * HD, W1a, W1a + 64 * HD, W1b, W1b + 64 * HD };

    cp_stage(sb, srcs[0], tid);
    // prologue: exclusive block-prefix scan (overlaps stage-0 load)
    if (tid < 128) {
        float c = 0.f;
        for (int p = 0; p < bk; p++) c += g_P[p][tid];
#pragma unroll
        for (int j = 0; j < 8; j++) {
            int n = base + j;
            float dv = rsqrtf((float)(n + 1));
            float h = g_h[n][tid];
            gs[j][tid] = fmaf(dv, c, dv * dv * h);
            c = fmaf(dv, h, c);
        }
    }
    float4 acc = ((const float4*)bg2)[lane];
    float4 aA = ((const float4*)b1)[lane];
    float4 aB = make_float4(0.f, 0.f, 0.f, 0.f);
#pragma unroll
    for (int s = 0; s < 6; s++) {
        if (s + 1 < 6) { cp_stage(sb + ((s + 1) & 1) * 32768, srcs[s + 1], tid); CP_WAIT1(); }
        else CP_WAIT0();
        __syncthreads();
        const float4* Ws4 = (const float4*)(buf + (s & 1) * 8192);
        const float* in = (s < 2) ? &gs[warp][0] : &hs[warp][0];
        int ko = (s & 1) * 64;
        float4 a = (s < 2) ? acc : ((s < 4) ? aA : aB);
#pragma unroll 8
        for (int k = 0; k < 64; k++) {
            float g = in[ko + k];
            float4 w = Ws4[k * 32 + lane];
            a.x = fmaf(g, w.x, a.x); a.y = fmaf(g, w.y, a.y);
            a.z = fmaf(g, w.z, a.z); a.w = fmaf(g, w.w, a.w);
        }
        if (s < 2) acc = a; else if (s < 4) aA = a; else aB = a;
        if (s == 1) {   // h3 = relu(acc)
            acc.x = fmaxf(acc.x, 0.f); acc.y = fmaxf(acc.y, 0.f);
            acc.z = fmaxf(acc.z, 0.f); acc.w = fmaxf(acc.w, 0.f);
            ((float4*)&hs[warp][0])[lane] = acc;
        }
        __syncthreads();
    }
    ((float4*)&g_A0[base + warp][0])[lane] = aA;
    ((float4*)&g_B0[base + warp][0])[lane] = aB;
}

// ---------------------------------------------------------------------------
// K3: blocks 0..135 : batch-0 pairwise tiles (16x16, upper triangle, mirrored)
//     blocks 136..147: constant fill for b>=1 (320 rows each, diag 0)
// grid 148 x 256
// ---------------------------------------------------------------------------
__global__ void k3(const float* __restrict__ W2, const float* __restrict__ b2,
                   float* __restrict__ out) {
    int tid = threadIdx.x;
    int blk = blockIdx.x;
    if (blk < 136) {
        int ti = 0, rem = blk;
        while (rem >= 16 - ti) { rem -= 16 - ti; ti++; }
        int tj = ti + rem;

        __shared__ __align__(16) float a_sh[16][132];
        __shared__ __align__(16) float b_sh[16][132];
        __shared__ __align__(16) float w2s[HD];
        __shared__ float b2s;
        __shared__ float tile[16][17];
        for (int i = tid; i < 512; i += 256) {
            int r = i >> 5, d4 = i & 31;
            ((float4*)&a_sh[r][0])[d4] = ((const float4*)&g_A0[ti * 16 + r][0])[d4];
            ((float4*)&b_sh[r][0])[d4] = ((const float4*)&g_B0[tj * 16 + r][0])[d4];
        }
        if (tid < HD) w2s[tid] = W2[tid];
        if (tid == 0) b2s = b2[0];
        __syncthreads();

        int il = tid >> 4, jl = tid & 15;
        const float4* a4 = (const float4*)&a_sh[il][0];
        const float4* b4 = (const float4*)&b_sh[jl][0];
        const float4* w4 = (const float4*)w2s;
        float ac0 = 0.f, ac1 = 0.f, ac2 = 0.f, ac3 = 0.f;
#pragma unroll
        for (int qd = 0; qd < 8; qd++) {
            { float4 a=a4[qd],    b=b4[qd],    w=w4[qd];
              ac0 = fmaf(fmaxf(a.x+b.x,0.f),w.x,ac0); ac0 = fmaf(fmaxf(a.y+b.y,0.f),w.y,ac0);
              ac0 = fmaf(fmaxf(a.z+b.z,0.f),w.z,ac0); ac0 = fmaf(fmaxf(a.w+b.w,0.f),w.w,ac0); }
            { float4 a=a4[qd+8],  b=b4[qd+8],  w=w4[qd+8];
              ac1 = fmaf(fmaxf(a.x+b.x,0.f),w.x,ac1); ac1 = fmaf(fmaxf(a.y+b.y,0.f),w.y,ac1);
              ac1 = fmaf(fmaxf(a.z+b.z,0.f),w.z,ac1); ac1 = fmaf(fmaxf(a.w+b.w,0.f),w.w,ac1); }
            { float4 a=a4[qd+16], b=b4[qd+16], w=w4[qd+16];
              ac2 = fmaf(fmaxf(a.x+b.x,0.f),w.x,ac2); ac2 = fmaf(fmaxf(a.y+b.y,0.f),w.y,ac2);
              ac2 = fmaf(fmaxf(a.z+b.z,0.f),w.z,ac2); ac2 = fmaf(fmaxf(a.w+b.w,0.f),w.w,ac2); }
            { float4 a=a4[qd+24], b=b4[qd+24], w=w4[qd+24];
              ac3 = fmaf(fmaxf(a.x+b.x,0.f),w.x,ac3); ac3 = fmaf(fmaxf(a.y+b.y,0.f),w.y,ac3);
              ac3 = fmaf(fmaxf(a.z+b.z,0.f),w.z,ac3); ac3 = fmaf(fmaxf(a.w+b.w,0.f),w.w,ac3); }
        }
        float accv = (ac0 + ac1) + (ac2 + ac3);
        tile[il][jl] = 1.f / (1.f + __expf(-(accv + b2s)));
        __syncthreads();

        int r = tid >> 4, c = tid & 15;
        if (ti == tj) {
            float vo = (r < c) ? tile[r][c] : ((r > c) ? tile[c][r] : 0.f);
            out[((size_t)(ti * 16 + r)) * NN + ti * 16 + c] = vo;
        } else {
            out[((size_t)(ti * 16 + r)) * NN + tj * 16 + c] = tile[r][c];
            out[((size_t)(tj * 16 + r)) * NN + ti * 16 + c] = tile[c][r];
        }
    } else {
        __shared__ float pbs[NB];
        if (tid < NB) pbs[tid] = g_pb[tid];
        __syncthreads();
        int fid = blk - 136;
        int f4base = fid * 20480;          // 320 rows * 64 float4 per block
#pragma unroll 4
        for (int t = 0; t < 80; t++) {
            int idx = f4base + t * 256 + tid;
            int gr = idx >> 6;             // fill row 0..3839
            int c4 = idx & 63;
            int b = (gr >> 8) + 1;
            int i = gr & 255;
            float p = pbs[b];
            int j0 = c4 * 4;
            float4 vo;
            vo.x = (i == j0 + 0) ? 0.f : p;
            vo.y = (i == j0 + 1) ? 0.f : p;
            vo.z = (i == j0 + 2) ? 0.f : p;
            vo.w = (i == j0 + 3) ? 0.f : p;
            ((float4*)out)[((size_t)b * NN * NN + (size_t)i * NN) / 4 + c4] = vo;
        }
    }
}

// ---------------------------------------------------------------------------
extern "C" void kernel_launch(void* const* d_in, const int* in_sizes, int n_in,
                              void* d_out, int out_size) {
    const float* z   = (const float*)d_in[0];
    const float* We  = (const float*)d_in[1];
    const float* be  = (const float*)d_in[2];
    const float* Wg  = (const float*)d_in[3];
    const float* bg  = (const float*)d_in[4];
    const float* W1a = (const float*)d_in[5];
    const float* W1b = (const float*)d_in[6];
    const float* b1  = (const float*)d_in[7];
    const float* W2  = (const float*)d_in[8];
    const float* b2  = (const float*)d_in[9];
    float* out = (float*)d_out;

    cudaFuncSetAttribute(k1, cudaFuncAttributeMaxDynamicSharedMemorySize, 65536);
    cudaFuncSetAttribute(k2, cudaFuncAttributeMaxDynamicSharedMemorySize, 65536);

    k1<<<47, 256, 65536>>>(z, We, be, Wg, bg, W1a, W1b, b1, W2, b2);
    k2<<<32, 256, 65536>>>(Wg + 2 * HD * HD, bg + 2 * HD, W1a, W1b, b1);
    k3<<<148, 256>>>(W2, b2, out);
}

// round 7
// speedup vs baseline: 1.0026x; 1.0026x over previous
#include <cuda_runtime.h>
#include <math.h>
#include <stdint.h>

#define HD 128
#define NN 256
#define NB 16
#define NBLK 128

// Scratch (allocation-free rule: __device__ globals)
__device__ float g_h[NN][HD];    // layer-2 output (relu)
__device__ float g_P[32][HD];    // per-block partial sums of dinv*h (scan)
__device__ float g_A0[NN][HD];   // h3 @ W1a + b1   (batch 0)
__device__ float g_B0[NN][HD];   // h3 @ W1b        (batch 0)
__device__ float g_pb[NB];       // constant edge prob per batch (b>=1)
__device__ unsigned g_cnt = 0;   // monotonic grid-barrier counter

// 32KB stage load via cp.async (8 x 16B per thread, 256 threads)
__device__ __forceinline__ void cp_stage(uint32_t dst, const float* src, int tid) {
    const char* s = (const char*)src + tid * 16;
    uint32_t d = dst + tid * 16;
#pragma unroll
    for (int i = 0; i < 8; i++)
        asm volatile("cp.async.cg.shared.global [%0], [%1], 16;"
                     :: "r"(d + i * 4096), "l"(s + i * 4096));
    asm volatile("cp.async.commit_group;" ::: "memory");
}
#define CPW2() asm volatile("cp.async.wait_group 2;" ::: "memory")
#define CPW1() asm volatile("cp.async.wait_group 1;" ::: "memory")
#define CPW0() asm volatile("cp.async.wait_group 0;" ::: "memory")

// grid barrier: monotonic counter, wrap-safe. All NBLK blocks co-resident
// (98KB+11KB smem/block, 227KB/SM => 2 blocks/SM => 128 blocks on >=64 SMs).
__device__ __forceinline__ void gsync(int tid) {
    __syncthreads();
    if (tid == 0) {
        __threadfence();
        unsigned v = atomicAdd(&g_cnt, 1u);
        unsigned target = (v & ~127u) + 128u;
        while ((int)(*(volatile unsigned*)&g_cnt - target) < 0) {}
    }
    __syncthreads();
}

// ---------------------------------------------------------------------------
// One fused kernel, grid 128 x 256, dynamic smem 96KB (3 x 32KB cp.async bufs)
// Phase A: blocks 0..31 batch-0 (emb->u->closed-form L1+scan->L2 GEMM, 5 stages)
//          blocks 32..46 node-constant chains b=1..15 (11 stages)
// Phase B: blocks 0..63 scan -> L3 GEMM+relu -> W1a|W1b GEMM (4 stages)
// Phase C: 136 pair tiles + 12 fill tasks over 128 blocks
// ---------------------------------------------------------------------------
__global__ void kfused(const float* __restrict__ z, const float* __restrict__ We,
                       const float* __restrict__ be, const float* __restrict__ Wg,
                       const float* __restrict__ bg, const float* __restrict__ W1a,
                       const float* __restrict__ W1b, const float* __restrict__ b1,
                       const float* __restrict__ W2, const float* __restrict__ b2,
                       float* __restrict__ out) {
    extern __shared__ __align__(16) float buf[];   // 3 x 8192 floats
    __shared__ __align__(16) float gs[8][HD];
    __shared__ __align__(16) float hs[8][HD];
    __shared__ float zs[64];
    __shared__ float vv[HD];
    __shared__ float red[2][HD];
    __shared__ float ds[NN];
    __shared__ float wsum[8];
    int tid = threadIdx.x, bk = blockIdx.x;
    int d = tid & 127, hf = tid >> 7;
    int warp = tid >> 5, lane = tid & 31;
    uint32_t sb = (uint32_t)__cvta_generic_to_shared(buf);

    // ======================= Phase A =======================
    if (bk < 32) {
        const float* srcs[5] = { We, Wg, Wg + 64 * HD,
                                 Wg + HD * HD, Wg + HD * HD + 64 * HD };
        cp_stage(sb,         srcs[0], tid);
        cp_stage(sb + 32768, srcs[1], tid);
        cp_stage(sb + 65536, srcs[2], tid);
        if (tid < 64) zs[tid] = z[tid];
        ds[tid] = rsqrtf((float)(tid + 1));
        float u = 0.f;
        float4 acc = make_float4(0.f, 0.f, 0.f, 0.f);
#pragma unroll
        for (int s = 0; s < 5; s++) {
            if (s < 3) { CPW2(); } else if (s == 3) { CPW1(); } else { CPW0(); }
            __syncthreads();
            const float* B = buf + (s % 3) * 8192;
            if (s == 0) {
                float p0 = 0.f, p1 = 0.f; int kb = hf * 32;
#pragma unroll 8
                for (int kk = 0; kk < 32; kk += 2) {
                    p0 = fmaf(zs[kb + kk],     B[(kb + kk) * HD + d],     p0);
                    p1 = fmaf(zs[kb + kk + 1], B[(kb + kk + 1) * HD + d], p1);
                }
                red[hf][d] = p0 + p1;
                __syncthreads();
                if (tid < 128) vv[d] = red[0][d] + red[1][d] + be[d];
            } else if (s <= 2) {
                int hh = s - 1;
                float p0 = 0.f, p1 = 0.f; int kb = hf * 32;
#pragma unroll 8
                for (int kk = 0; kk < 32; kk += 2) {
                    p0 = fmaf(vv[hh * 64 + kb + kk],     B[(kb + kk) * HD + d],     p0);
                    p1 = fmaf(vv[hh * 64 + kb + kk + 1], B[(kb + kk + 1) * HD + d], p1);
                }
                u += p0 + p1;
                if (s == 2) {
                    red[hf][d] = u;
                    __syncthreads();
                    if (tid < 128) {
                        float uf = red[0][d] + red[1][d];
                        float bg0 = bg[d];
                        float c = 0.f, Dex = 0.f;
                        int base = bk * 8;
                        for (int j = 0; j < base + 8; j++) {
                            float dv = ds[j];
                            float sc = fmaf(dv, Dex, dv * dv);
                            float h1 = fmaxf(fmaf(sc, uf, bg0), 0.f);
                            if (j >= base) gs[j - base][d] = fmaf(dv, c, dv * dv * h1);
                            c = fmaf(dv, h1, c);
                            Dex += dv;
                        }
                    }
                }
            } else {
                if (s == 3) acc = ((const float4*)(bg + HD))[lane];
                const float4* Ws4 = (const float4*)B;
                int ko = (s - 3) * 64;
#pragma unroll 8
                for (int k = 0; k < 64; k++) {
                    float g = gs[warp][ko + k];
                    float4 w = Ws4[k * 32 + lane];
                    acc.x = fmaf(g, w.x, acc.x); acc.y = fmaf(g, w.y, acc.y);
                    acc.z = fmaf(g, w.z, acc.z); acc.w = fmaf(g, w.w, acc.w);
                }
            }
            __syncthreads();
            if (s < 2) cp_stage(sb + (s % 3) * 32768, srcs[s + 3], tid);
        }
        acc.x = fmaxf(acc.x, 0.f); acc.y = fmaxf(acc.y, 0.f);
        acc.z = fmaxf(acc.z, 0.f); acc.w = fmaxf(acc.w, 0.f);
        int base = bk * 8;
        ((float4*)&g_h[base + warp][0])[lane] = acc;
        float dj = ds[base + warp];
        ((float4*)&hs[warp][0])[lane] = make_float4(acc.x * dj, acc.y * dj, acc.z * dj, acc.w * dj);
        __syncthreads();
        if (tid < HD) {
            float sum = 0.f;
#pragma unroll
            for (int w = 0; w < 8; w++) sum += hs[w][tid];
            g_P[bk][tid] = sum;
        }
    } else if (bk < 47) {
        int b = bk - 31;
        const float* srcs[11] = { We,
            Wg,               Wg + 64 * HD,
            Wg + HD * HD,     Wg + HD * HD + 64 * HD,
            Wg + 2 * HD * HD, Wg + 2 * HD * HD + 64 * HD,
            W1a,              W1a + 64 * HD,
            W1b,              W1b + 64 * HD };
        cp_stage(sb,         srcs[0], tid);
        cp_stage(sb + 32768, srcs[1], tid);
        cp_stage(sb + 65536, srcs[2], tid);
        if (tid < 64) zs[tid] = z[b * 64 + tid];
        float accL = 0.f, aA = 0.f, aB = 0.f, aAf = 0.f;
#pragma unroll
        for (int s = 0; s < 11; s++) {
            if (s < 9) { CPW2(); } else if (s == 9) { CPW1(); } else { CPW0(); }
            __syncthreads();
            const float* B = buf + (s % 3) * 8192;
            if (s == 0) {
                float p0 = 0.f, p1 = 0.f; int kb = hf * 32;
#pragma unroll 8
                for (int kk = 0; kk < 32; kk += 2) {
                    p0 = fmaf(zs[kb + kk],     B[(kb + kk) * HD + d],     p0);
                    p1 = fmaf(zs[kb + kk + 1], B[(kb + kk + 1) * HD + d], p1);
                }
                red[hf][d] = p0 + p1;
                __syncthreads();
                if (tid < 128) vv[d] = red[0][d] + red[1][d] + be[d];
            } else {
                int g = (s - 1) >> 1, hh = (s - 1) & 1;
                float p0 = 0.f, p1 = 0.f; int kb = hf * 32;
#pragma unroll 8
                for (int kk = 0; kk < 32; kk += 2) {
                    p0 = fmaf(vv[hh * 64 + kb + kk],     B[(kb + kk) * HD + d],     p0);
                    p1 = fmaf(vv[hh * 64 + kb + kk + 1], B[(kb + kk + 1) * HD + d], p1);
                }
                float pt = p0 + p1;
                if (s <= 6) accL += pt;
                else if (s <= 8) aA += pt;
                else aB += pt;
                if (hh == 1 && g < 3) {        // GCN layer boundary
                    red[hf][d] = accL;
                    __syncthreads();
                    if (tid < 128) vv[d] = fmaxf(red[0][d] + red[1][d] + bg[g * HD + d], 0.f);
                    accL = 0.f;
                }
                if (s == 8) {                  // W1a done
                    red[hf][d] = aA;
                    __syncthreads();
                    if (tid < 128) aAf = red[0][d] + red[1][d] + b1[d];
                }
            }
            __syncthreads();
            if (s < 8) cp_stage(sb + (s % 3) * 32768, srcs[s + 3], tid);
        }
        red[hf][d] = aB;
        __syncthreads();
        float t = 0.f;
        if (tid < 128) t = fmaxf(aAf + red[0][d] + red[1][d], 0.f) * W2[d];
        for (int off = 16; off > 0; off >>= 1)
            t += __shfl_down_sync(0xffffffffu, t, off);
        if ((tid & 31) == 0) wsum[tid >> 5] = t;
        __syncthreads();
        if (tid == 0) {
            float ssum = wsum[0] + wsum[1] + wsum[2] + wsum[3]
                       + wsum[4] + wsum[5] + wsum[6] + wsum[7] + b2[0];
            g_pb[b] = 1.f / (1.f + __expf(-ssum));
        }
    }

    gsync(tid);

    // ======================= Phase B =======================
    if (bk < 64) {
        int bk2 = bk >> 1, sel = bk & 1;
        int base = bk2 * 8;
        const float* Wg2 = Wg + 2 * HD * HD;
        const float* WX = sel ? W1b : W1a;
        const float* srcs[4] = { Wg2, Wg2 + 64 * HD, WX, WX + 64 * HD };
        cp_stage(sb,         srcs[0], tid);
        cp_stage(sb + 32768, srcs[1], tid);
        cp_stage(sb + 65536, srcs[2], tid);
        // scan prologue (overlaps the 3 prefetches)
        if (tid < 128) {
            float c = 0.f;
            for (int p = 0; p < bk2; p++) c += g_P[p][tid];
#pragma unroll
            for (int j = 0; j < 8; j++) {
                int n = base + j;
                float dv = rsqrtf((float)(n + 1));
                float h = g_h[n][tid];
                gs[j][tid] = fmaf(dv, c, dv * dv * h);
                c = fmaf(dv, h, c);
            }
        }
        float4 acc = ((const float4*)(bg + 2 * HD))[lane];
        float4 aX = sel ? make_float4(0.f, 0.f, 0.f, 0.f)
                        : ((const float4*)b1)[lane];
#pragma unroll
        for (int s = 0; s < 4; s++) {
            if (s < 2) { CPW2(); } else if (s == 2) { CPW1(); } else { CPW0(); }
            __syncthreads();
            const float4* Ws4 = (const float4*)(buf + (s % 3) * 8192);
            const float* in = (s < 2) ? &gs[warp][0] : &hs[warp][0];
            int ko = (s & 1) * 64;
            float4 a = (s < 2) ? acc : aX;
#pragma unroll 8
            for (int k = 0; k < 64; k++) {
                float g = in[ko + k];
                float4 w = Ws4[k * 32 + lane];
                a.x = fmaf(g, w.x, a.x); a.y = fmaf(g, w.y, a.y);
                a.z = fmaf(g, w.z, a.z); a.w = fmaf(g, w.w, a.w);
            }
            if (s < 2) acc = a; else aX = a;
            if (s == 1) {   // h3 = relu(acc)
                acc.x = fmaxf(acc.x, 0.f); acc.y = fmaxf(acc.y, 0.f);
                acc.z = fmaxf(acc.z, 0.f); acc.w = fmaxf(acc.w, 0.f);
                ((float4*)&hs[warp][0])[lane] = acc;
            }
            __syncthreads();
            if (s < 1) cp_stage(sb + (s % 3) * 32768, srcs[s + 3], tid);
        }
        if (sel) ((float4*)&g_B0[base + warp][0])[lane] = aX;
        else     ((float4*)&g_A0[base + warp][0])[lane] = aX;
    }

    gsync(tid);

    // ======================= Phase C =======================
    // overlay in buf: a_sh[16][132] @0, b_sh[16][132] @2112, w2s[128] @4224,
    // tile[16][17] @4356, b2s @4632
    float* a_sh = buf;
    float* b_sh = buf + 2112;
    float* w2s  = buf + 4224;
    float* tile = buf + 4356;
#pragma unroll 1
    for (int task = bk; task < 148; task += NBLK) {
        if (task < 136) {
            int ti = 0, rem = task;
            while (rem >= 16 - ti) { rem -= 16 - ti; ti++; }
            int tj = ti + rem;
            for (int i = tid; i < 512; i += 256) {
                int r = i >> 5, d4 = i & 31;
                ((float4*)&a_sh[r * 132])[d4] = ((const float4*)&g_A0[ti * 16 + r][0])[d4];
                ((float4*)&b_sh[r * 132])[d4] = ((const float4*)&g_B0[tj * 16 + r][0])[d4];
            }
            if (tid < HD) w2s[tid] = W2[tid];
            if (tid == 0) buf[4632] = b2[0];
            __syncthreads();

            int il = tid >> 4, jl = tid & 15;
            const float4* a4 = (const float4*)&a_sh[il * 132];
            const float4* b4 = (const float4*)&b_sh[jl * 132];
            const float4* w4 = (const float4*)w2s;
            float ac0 = 0.f, ac1 = 0.f, ac2 = 0.f, ac3 = 0.f;
#pragma unroll
            for (int qd = 0; qd < 8; qd++) {
                { float4 a = a4[qd],    b = b4[qd],    w = w4[qd];
                  ac0 = fmaf(fmaxf(a.x+b.x,0.f),w.x,ac0); ac0 = fmaf(fmaxf(a.y+b.y,0.f),w.y,ac0);
                  ac0 = fmaf(fmaxf(a.z+b.z,0.f),w.z,ac0); ac0 = fmaf(fmaxf(a.w+b.w,0.f),w.w,ac0); }
                { float4 a = a4[qd+8],  b = b4[qd+8],  w = w4[qd+8];
                  ac1 = fmaf(fmaxf(a.x+b.x,0.f),w.x,ac1); ac1 = fmaf(fmaxf(a.y+b.y,0.f),w.y,ac1);
                  ac1 = fmaf(fmaxf(a.z+b.z,0.f),w.z,ac1); ac1 = fmaf(fmaxf(a.w+b.w,0.f),w.w,ac1); }
                { float4 a = a4[qd+16], b = b4[qd+16], w = w4[qd+16];
                  ac2 = fmaf(fmaxf(a.x+b.x,0.f),w.x,ac2); ac2 = fmaf(fmaxf(a.y+b.y,0.f),w.y,ac2);
                  ac2 = fmaf(fmaxf(a.z+b.z,0.f),w.z,ac2); ac2 = fmaf(fmaxf(a.w+b.w,0.f),w.w,ac2); }
                { float4 a = a4[qd+24], b = b4[qd+24], w = w4[qd+24];
                  ac3 = fmaf(fmaxf(a.x+b.x,0.f),w.x,ac3); ac3 = fmaf(fmaxf(a.y+b.y,0.f),w.y,ac3);
                  ac3 = fmaf(fmaxf(a.z+b.z,0.f),w.z,ac3); ac3 = fmaf(fmaxf(a.w+b.w,0.f),w.w,ac3); }
            }
            float accv = (ac0 + ac1) + (ac2 + ac3);
            tile[il * 17 + jl] = 1.f / (1.f + __expf(-(accv + buf[4632])));
            __syncthreads();

            int r = tid >> 4, c = tid & 15;
            if (ti == tj) {
                float vo = (r < c) ? tile[r * 17 + c] : ((r > c) ? tile[c * 17 + r] : 0.f);
                out[((size_t)(ti * 16 + r)) * NN + ti * 16 + c] = vo;
            } else {
                out[((size_t)(ti * 16 + r)) * NN + tj * 16 + c] = tile[r * 17 + c];
                out[((size_t)(tj * 16 + r)) * NN + ti * 16 + c] = tile[c * 17 + r];
            }
            __syncthreads();   // before buf reuse by next task
        } else {
            int fid = task - 136;
            int f4base = fid * 20480;      // 320 rows * 64 float4 per task
#pragma unroll 4
            for (int t = 0; t < 80; t++) {
                int idx = f4base + t * 256 + tid;
                int gr = idx >> 6;
                int c4 = idx & 63;
                int b = (gr >> 8) + 1;
                int i = gr & 255;
                float p = g_pb[b];
                int j0 = c4 * 4;
                float4 vo;
                vo.x = (i == j0 + 0) ? 0.f : p;
                vo.y = (i == j0 + 1) ? 0.f : p;
                vo.z = (i == j0 + 2) ? 0.f : p;
                vo.w = (i == j0 + 3) ? 0.f : p;
                ((float4*)out)[((size_t)b * NN * NN + (size_t)i * NN) / 4 + c4] = vo;
            }
        }
    }
}

// ---------------------------------------------------------------------------
extern "C" void kernel_launch(void* const* d_in, const int* in_sizes, int n_in,
                              void* d_out, int out_size) {
    const float* z   = (const float*)d_in[0];
    const float* We  = (const float*)d_in[1];
    const float* be  = (const float*)d_in[2];
    const float* Wg  = (const float*)d_in[3];
    const float* bg  = (const float*)d_in[4];
    const float* W1a = (const float*)d_in[5];
    const float* W1b = (const float*)d_in[6];
    const float* b1  = (const float*)d_in[7];
    const float* W2  = (const float*)d_in[8];
    const float* b2  = (const float*)d_in[9];
    float* out = (float*)d_out;

    cudaFuncSetAttribute(kfused, cudaFuncAttributeMaxDynamicSharedMemorySize, 98304);
    kfused<<<NBLK, 256, 98304>>>(z, We, be, Wg, bg, W1a, W1b, b1, W2, b2, out);
}

// round 9
// speedup vs baseline: 1.1249x; 1.1220x over previous
#include <cuda_runtime.h>
#include <math.h>
#include <stdint.h>

#define HD 128
#define NN 256
#define NB 16

// Scratch (allocation-free rule: __device__ globals)
__device__ float g_h[NN][HD];    // layer-2 output (relu)
__device__ float g_P[32][HD];    // per-block partial sums of dinv*h (scan)
__device__ float g_A0[NN][HD];   // h3 @ W1a + b1   (batch 0)
__device__ float g_B0[NN][HD];   // h3 @ W1b        (batch 0)
__device__ float g_pb[NB];       // constant edge prob per batch (b>=1)

// 32KB stage load via cp.async (8 x 16B per thread, 256 threads)
__device__ __forceinline__ void cp_stage(uint32_t dst, const float* src, int tid) {
    const char* s = (const char*)src + tid * 16;
    uint32_t d = dst + tid * 16;
#pragma unroll
    for (int i = 0; i < 8; i++)
        asm volatile("cp.async.cg.shared.global [%0], [%1], 16;"
                     :: "r"(d + i * 4096), "l"(s + i * 4096));
    asm volatile("cp.async.commit_group;" ::: "memory");
}
#define CPWG4() asm volatile("cp.async.wait_group 4;" ::: "memory")
#define CPWG3() asm volatile("cp.async.wait_group 3;" ::: "memory")
#define CPWG2() asm volatile("cp.async.wait_group 2;" ::: "memory")
#define CPWG1() asm volatile("cp.async.wait_group 1;" ::: "memory")
#define CPWG0() asm volatile("cp.async.wait_group 0;" ::: "memory")

// ---------------------------------------------------------------------------
// K1: blocks 0..31  : batch-0 (emb->u->closed-form L1+scan->L2 GEMM),
//                     ALL 5 stage loads issued up-front (latency paid once).
//     blocks 32..46 : node-constant chains b=1..15, 11 stages through a
//                     5-deep cp.async ring (lookahead ~5 stage-times).
// grid 47 x 256, dynamic smem 160KB (5 x 32KB) -> 1 block/SM
// ---------------------------------------------------------------------------
__global__ void __launch_bounds__(256, 1)
k1(const float* __restrict__ z, const float* __restrict__ We,
   const float* __restrict__ be, const float* __restrict__ Wg,
   const float* __restrict__ bg, const float* __restrict__ W1a,
   const float* __restrict__ W1b, const float* __restrict__ b1,
   const float* __restrict__ W2, const float* __restrict__ b2) {
    extern __shared__ __align__(16) float buf[];   // 5 x 8192 floats
    __shared__ __align__(16) float gs[8][HD];
    __shared__ __align__(16) float hs[8][HD];
    __shared__ float zs[64];
    __shared__ float vv[HD];
    __shared__ float red[2][HD];
    __shared__ float ds[NN];
    __shared__ float wsum[8];
    int tid = threadIdx.x, bk = blockIdx.x;
    int d = tid & 127, hf = tid >> 7;
    int warp = tid >> 5, lane = tid & 31;
    uint32_t sb = (uint32_t)__cvta_generic_to_shared(buf);

    if (bk < 32) {
        // ---- batch-0 path: 5 stages, all loads issued at t=0 ----
        const float* srcs[5] = { We, Wg, Wg + 64 * HD,
                                 Wg + HD * HD, Wg + HD * HD + 64 * HD };
#pragma unroll
        for (int i = 0; i < 5; i++) cp_stage(sb + i * 32768u, srcs[i], tid);
        if (tid < 64) zs[tid] = z[tid];
        ds[tid] = rsqrtf((float)(tid + 1));
        float u = 0.f;
        float4 acc = make_float4(0.f, 0.f, 0.f, 0.f);
#pragma unroll
        for (int s = 0; s < 5; s++) {
            if (s == 0) { CPWG4(); } else if (s == 1) { CPWG3(); }
            else if (s == 2) { CPWG2(); } else if (s == 3) { CPWG1(); }
            else { CPWG0(); }
            __syncthreads();
            const float* B = buf + s * 8192;
            if (s == 0) {
                float p0 = 0.f, p1 = 0.f; int kb = hf * 32;
#pragma unroll 8
                for (int kk = 0; kk < 32; kk += 2) {
                    p0 = fmaf(zs[kb + kk],     B[(kb + kk) * HD + d],     p0);
                    p1 = fmaf(zs[kb + kk + 1], B[(kb + kk + 1) * HD + d], p1);
                }
                red[hf][d] = p0 + p1;
                __syncthreads();
                if (tid < 128) vv[d] = red[0][d] + red[1][d] + be[d];
            } else if (s <= 2) {
                int hh = s - 1;
                float p0 = 0.f, p1 = 0.f; int kb = hf * 32;
#pragma unroll 8
                for (int kk = 0; kk < 32; kk += 2) {
                    p0 = fmaf(vv[hh * 64 + kb + kk],     B[(kb + kk) * HD + d],     p0);
                    p1 = fmaf(vv[hh * 64 + kb + kk + 1], B[(kb + kk + 1) * HD + d], p1);
                }
                u += p0 + p1;
                if (s == 2) {
                    red[hf][d] = u;
                    __syncthreads();
                    if (tid < 128) {
                        // closed-form layer-1 + exclusive dinv-scan to this block
                        float uf = red[0][d] + red[1][d];
                        float bg0 = bg[d];
                        float c = 0.f, Dex = 0.f;
                        int base = bk * 8;
                        for (int j = 0; j < base + 8; j++) {
                            float dv = ds[j];
                            float sc = fmaf(dv, Dex, dv * dv);
                            float h1 = fmaxf(fmaf(sc, uf, bg0), 0.f);
                            if (j >= base) gs[j - base][d] = fmaf(dv, c, dv * dv * h1);
                            c = fmaf(dv, h1, c);
                            Dex += dv;
                        }
                    }
                }
            } else {
                if (s == 3) acc = ((const float4*)(bg + HD))[lane];
                const float4* Ws4 = (const float4*)B;
                int ko = (s - 3) * 64;
#pragma unroll 8
                for (int k = 0; k < 64; k++) {
                    float g = gs[warp][ko + k];
                    float4 w = Ws4[k * 32 + lane];
                    acc.x = fmaf(g, w.x, acc.x); acc.y = fmaf(g, w.y, acc.y);
                    acc.z = fmaf(g, w.z, acc.z); acc.w = fmaf(g, w.w, acc.w);
                }
            }
            __syncthreads();
        }
        acc.x = fmaxf(acc.x, 0.f); acc.y = fmaxf(acc.y, 0.f);
        acc.z = fmaxf(acc.z, 0.f); acc.w = fmaxf(acc.w, 0.f);
        int base = bk * 8;
        ((float4*)&g_h[base + warp][0])[lane] = acc;
        float dj = ds[base + warp];
        ((float4*)&hs[warp][0])[lane] = make_float4(acc.x * dj, acc.y * dj, acc.z * dj, acc.w * dj);
        __syncthreads();
        if (tid < HD) {
            float sum = 0.f;
#pragma unroll
            for (int w = 0; w < 8; w++) sum += hs[w][tid];
            g_P[bk][tid] = sum;
        }
    } else if (bk < 47) {
        // ---- node-constant chain for batch b = bk-31: 11 stages, ring-5 ----
        int b = bk - 31;
        const float* srcs[11] = { We,
            Wg,               Wg + 64 * HD,
            Wg + HD * HD,     Wg + HD * HD + 64 * HD,
            Wg + 2 * HD * HD, Wg + 2 * HD * HD + 64 * HD,
            W1a,              W1a + 64 * HD,
            W1b,              W1b + 64 * HD };
#pragma unroll
        for (int i = 0; i < 5; i++) cp_stage(sb + i * 32768u, srcs[i], tid);
        if (tid < 64) zs[tid] = z[b * 64 + tid];
        float accL = 0.f, aA = 0.f, aB = 0.f, aAf = 0.f;
#pragma unroll
        for (int s = 0; s < 11; s++) {
            if (s <= 6) { CPWG4(); } else if (s == 7) { CPWG3(); }
            else if (s == 8) { CPWG2(); } else if (s == 9) { CPWG1(); }
            else { CPWG0(); }
            __syncthreads();
            const float* B = buf + (s % 5) * 8192;
            if (s == 0) {
                float p0 = 0.f, p1 = 0.f; int kb = hf * 32;
#pragma unroll 8
                for (int kk = 0; kk < 32; kk += 2) {
                    p0 = fmaf(zs[kb + kk],     B[(kb + kk) * HD + d],     p0);
                    p1 = fmaf(zs[kb + kk + 1], B[(kb + kk + 1) * HD + d], p1);
                }
                red[hf][d] = p0 + p1;
                __syncthreads();
                if (tid < 128) vv[d] = red[0][d] + red[1][d] + be[d];
            } else {
                int g = (s - 1) >> 1, hh = (s - 1) & 1;
                float p0 = 0.f, p1 = 0.f; int kb = hf * 32;
#pragma unroll 8
                for (int kk = 0; kk < 32; kk += 2) {
                    p0 = fmaf(vv[hh * 64 + kb + kk],     B[(kb + kk) * HD + d],     p0);
                    p1 = fmaf(vv[hh * 64 + kb + kk + 1], B[(kb + kk + 1) * HD + d], p1);
                }
                float pt = p0 + p1;
                if (s <= 6) accL += pt;
                else if (s <= 8) aA += pt;
                else aB += pt;
                if (hh == 1 && g < 3) {        // GCN layer boundary
                    red[hf][d] = accL;
                    __syncthreads();
                    if (tid < 128) vv[d] = fmaxf(red[0][d] + red[1][d] + bg[g * HD + d], 0.f);
                    accL = 0.f;
                }
                if (s == 8) {                  // W1a done
                    red[hf][d] = aA;
                    __syncthreads();
                    if (tid < 128) aAf = red[0][d] + red[1][d] + b1[d];
                }
            }
            __syncthreads();
            if (s + 5 < 11) cp_stage(sb + (s % 5) * 32768u, srcs[s + 5], tid);
        }
        red[hf][d] = aB;
        __syncthreads();
        float t = 0.f;
        if (tid < 128) t = fmaxf(aAf + red[0][d] + red[1][d], 0.f) * W2[d];
        for (int off = 16; off > 0; off >>= 1)
            t += __shfl_down_sync(0xffffffffu, t, off);
        if ((tid & 31) == 0) wsum[tid >> 5] = t;
        __syncthreads();
        if (tid == 0) {
            float ssum = wsum[0] + wsum[1] + wsum[2] + wsum[3]
                       + wsum[4] + wsum[5] + wsum[6] + wsum[7] + b2[0];
            g_pb[b] = 1.f / (1.f + __expf(-ssum));
        }
    }
}

// ---------------------------------------------------------------------------
// K2: scan (prefetched, MLP'd) -> layer-3 GEMM+relu -> W1a|W1b GEMM.
// 4 stages, ALL loads issued up-front. grid 64 x 256, dynamic smem 128KB.
// blk = bk2*2 + sel (sel 0 -> W1a/g_A0, 1 -> W1b/g_B0)
// ---------------------------------------------------------------------------
__global__ void __launch_bounds__(256, 1)
k2(const float* __restrict__ Wg2, const float* __restrict__ bg2,
   const float* __restrict__ W1a, const float* __restrict__ W1b,
   const float* __restrict__ b1) {
    extern __shared__ __align__(16) float buf[];   // 4 x 8192 floats
    __shared__ __align__(16) float gs[8][HD];
    __shared__ __align__(16) float hs[8][HD];
    int tid = threadIdx.x;
    int bk2 = blockIdx.x >> 1, sel = blockIdx.x & 1;
    int base = bk2 * 8;
    int warp = tid >> 5, lane = tid & 31;
    uint32_t sb = (uint32_t)__cvta_generic_to_shared(buf);
    const float* WX = sel ? W1b : W1a;
    const float* srcs[4] = { Wg2, Wg2 + 64 * HD, WX, WX + 64 * HD };
#pragma unroll
    for (int i = 0; i < 4; i++) cp_stage(sb + i * 32768u, srcs[i], tid);

    // prologue: prefetched scan (overlaps all 4 in-flight loads)
    if (tid < 128) {
        float hr[8];
#pragma unroll
        for (int j = 0; j < 8; j++) hr[j] = g_h[base + j][tid];   // 8 MLP'd loads
        float ca[4] = {0.f, 0.f, 0.f, 0.f};
#pragma unroll
        for (int p = 0; p < 32; p++) {                             // 32 MLP'd loads
            float v = g_P[p][tid];
            ca[p & 3] += (p < bk2) ? v : 0.f;
        }
        float c = (ca[0] + ca[1]) + (ca[2] + ca[3]);
#pragma unroll
        for (int j = 0; j < 8; j++) {
            float dv = rsqrtf((float)(base + j + 1));
            gs[j][tid] = fmaf(dv, c, dv * dv * hr[j]);
            c = fmaf(dv, hr[j], c);
        }
    }
    float4 acc = ((const float4*)bg2)[lane];
    float4 aX = sel ? make_float4(0.f, 0.f, 0.f, 0.f)
                    : ((const float4*)b1)[lane];
#pragma unroll
    for (int s = 0; s < 4; s++) {
        if (s == 0) { CPWG3(); } else if (s == 1) { CPWG2(); }
        else if (s == 2) { CPWG1(); } else { CPWG0(); }
        __syncthreads();
        const float4* Ws4 = (const float4*)(buf + s * 8192);
        const float* in = (s < 2) ? &gs[warp][0] : &hs[warp][0];
        int ko = (s & 1) * 64;
        float4 a = (s < 2) ? acc : aX;
#pragma unroll 8
        for (int k = 0; k < 64; k++) {
            float g = in[ko + k];
            float4 w = Ws4[k * 32 + lane];
            a.x = fmaf(g, w.x, a.x); a.y = fmaf(g, w.y, a.y);
            a.z = fmaf(g, w.z, a.z); a.w = fmaf(g, w.w, a.w);
        }
        if (s < 2) acc = a; else aX = a;
        if (s == 1) {   // h3 = relu(acc)
            acc.x = fmaxf(acc.x, 0.f); acc.y = fmaxf(acc.y, 0.f);
            acc.z = fmaxf(acc.z, 0.f); acc.w = fmaxf(acc.w, 0.f);
            ((float4*)&hs[warp][0])[lane] = acc;
        }
        __syncthreads();
    }
    if (sel) ((float4*)&g_B0[base + warp][0])[lane] = aX;
    else     ((float4*)&g_A0[base + warp][0])[lane] = aX;
}

// ---------------------------------------------------------------------------
// K3: blocks 0..135 : batch-0 pairwise tiles (16x16, upper triangle, mirrored)
//     blocks 136..147: constant fill for b>=1 (320 rows each, diag 0)
// grid 148 x 256 (one wave)
// ---------------------------------------------------------------------------
__global__ void k3(const float* __restrict__ W2, const float* __restrict__ b2,
                   float* __restrict__ out) {
    int tid = threadIdx.x;
    int blk = blockIdx.x;
    if (blk < 136) {
        int ti = 0, rem = blk;
        while (rem >= 16 - ti) { rem -= 16 - ti; ti++; }
        int tj = ti + rem;

        __shared__ __align__(16) float a_sh[16][132];
        __shared__ __align__(16) float b_sh[16][132];
        __shared__ __align__(16) float w2s[HD];
        __shared__ float b2s;
        __shared__ float tile[16][17];
        for (int i = tid; i < 512; i += 256) {
            int r = i >> 5, d4 = i & 31;
            ((float4*)&a_sh[r][0])[d4] = ((const float4*)&g_A0[ti * 16 + r][0])[d4];
            ((float4*)&b_sh[r][0])[d4] = ((const float4*)&g_B0[tj * 16 + r][0])[d4];
        }
        if (tid < HD) w2s[tid] = W2[tid];
        if (tid == 0) b2s = b2[0];
        __syncthreads();

        int il = tid >> 4, jl = tid & 15;
        const float4* a4 = (const float4*)&a_sh[il][0];
        const float4* b4 = (const float4*)&b_sh[jl][0];
        const float4* w4 = (const float4*)w2s;
        float ac0 = 0.f, ac1 = 0.f, ac2 = 0.f, ac3 = 0.f;
#pragma unroll
        for (int qd = 0; qd < 8; qd++) {
            { float4 a=a4[qd],    b=b4[qd],    w=w4[qd];
              ac0 = fmaf(fmaxf(a.x+b.x,0.f),w.x,ac0); ac0 = fmaf(fmaxf(a.y+b.y,0.f),w.y,ac0);
              ac0 = fmaf(fmaxf(a.z+b.z,0.f),w.z,ac0); ac0 = fmaf(fmaxf(a.w+b.w,0.f),w.w,ac0); }
            { float4 a=a4[qd+8],  b=b4[qd+8],  w=w4[qd+8];
              ac1 = fmaf(fmaxf(a.x+b.x,0.f),w.x,ac1); ac1 = fmaf(fmaxf(a.y+b.y,0.f),w.y,ac1);
              ac1 = fmaf(fmaxf(a.z+b.z,0.f),w.z,ac1); ac1 = fmaf(fmaxf(a.w+b.w,0.f),w.w,ac1); }
            { float4 a=a4[qd+16], b=b4[qd+16], w=w4[qd+16];
              ac2 = fmaf(fmaxf(a.x+b.x,0.f),w.x,ac2); ac2 = fmaf(fmaxf(a.y+b.y,0.f),w.y,ac2);
              ac2 = fmaf(fmaxf(a.z+b.z,0.f),w.z,ac2); ac2 = fmaf(fmaxf(a.w+b.w,0.f),w.w,ac2); }
            { float4 a=a4[qd+24], b=b4[qd+24], w=w4[qd+24];
              ac3 = fmaf(fmaxf(a.x+b.x,0.f),w.x,ac3); ac3 = fmaf(fmaxf(a.y+b.y,0.f),w.y,ac3);
              ac3 = fmaf(fmaxf(a.z+b.z,0.f),w.z,ac3); ac3 = fmaf(fmaxf(a.w+b.w,0.f),w.w,ac3); }
        }
        float accv = (ac0 + ac1) + (ac2 + ac3);
        tile[il][jl] = 1.f / (1.f + __expf(-(accv + b2s)));
        __syncthreads();

        int r = tid >> 4, c = tid & 15;
        if (ti == tj) {
            float vo = (r < c) ? tile[r][c] : ((r > c) ? tile[c][r] : 0.f);
            out[((size_t)(ti * 16 + r)) * NN + ti * 16 + c] = vo;
        } else {
            out[((size_t)(ti * 16 + r)) * NN + tj * 16 + c] = tile[r][c];
            out[((size_t)(tj * 16 + r)) * NN + ti * 16 + c] = tile[c][r];
        }
    } else {
        __shared__ float pbs[NB];
        if (tid < NB) pbs[tid] = g_pb[tid];
        __syncthreads();
        int fid = blk - 136;
        int f4base = fid * 20480;          // 320 rows * 64 float4 per block
#pragma unroll 4
        for (int t = 0; t < 80; t++) {
            int idx = f4base + t * 256 + tid;
            int gr = idx >> 6;             // fill row 0..3839
            int c4 = idx & 63;
            int b = (gr >> 8) + 1;
            int i = gr & 255;
            float p = pbs[b];
            int j0 = c4 * 4;
            float4 vo;
            vo.x = (i == j0 + 0) ? 0.f : p;
            vo.y = (i == j0 + 1) ? 0.f : p;
            vo.z = (i == j0 + 2) ? 0.f : p;
            vo.w = (i == j0 + 3) ? 0.f : p;
            ((float4*)out)[((size_t)b * NN * NN + (size_t)i * NN) / 4 + c4] = vo;
        }
    }
}

// ---------------------------------------------------------------------------
extern "C" void kernel_launch(void* const* d_in, const int* in_sizes, int n_in,
                              void* d_out, int out_size) {
    const float* z   = (const float*)d_in[0];
    const float* We  = (const float*)d_in[1];
    const float* be  = (const float*)d_in[2];
    const float* Wg  = (const float*)d_in[3];
    const float* bg  = (const float*)d_in[4];
    const float* W1a = (const float*)d_in[5];
    const float* W1b = (const float*)d_in[6];
    const float* b1  = (const float*)d_in[7];
    const float* W2  = (const float*)d_in[8];
    const float* b2  = (const float*)d_in[9];
    float* out = (float*)d_out;

    cudaFuncSetAttribute(k1, cudaFuncAttributeMaxDynamicSharedMemorySize, 163840);
    cudaFuncSetAttribute(k2, cudaFuncAttributeMaxDynamicSharedMemorySize, 131072);

    k1<<<47, 256, 163840>>>(z, We, be, Wg, bg, W1a, W1b, b1, W2, b2);
    k2<<<64, 256, 131072>>>(Wg + 2 * HD * HD, bg + 2 * HD, W1a, W1b, b1);
    k3<<<148, 256>>>(W2, b2, out);
}

// round 10
// speedup vs baseline: 1.1304x; 1.0049x over previous
#include <cuda_runtime.h>
#include <math.h>
#include <stdint.h>

#define HD 128
#define NN 256
#define NB 16

// Scratch (allocation-free rule: __device__ globals)
__device__ float g_h[NN][HD];    // layer-2 output (relu)
__device__ float g_P[32][HD];    // per-block partial sums of dinv*h (scan)
__device__ float g_v3[NB][HD];   // post-layer-3 vector per batch b>=1
__device__ float g_A0[NN][HD];   // h3 @ W1a + b1   (batch 0)
__device__ float g_B0[NN][HD];   // h3 @ W1b        (batch 0)
__device__ float g_pb[NB];       // constant edge prob per batch (b>=1)

// 32KB stage load via cp.async (8 x 16B per thread, 256 threads)
__device__ __forceinline__ void cp_stage(uint32_t dst, const float* src, int tid) {
    const char* s = (const char*)src + tid * 16;
    uint32_t d = dst + tid * 16;
#pragma unroll
    for (int i = 0; i < 8; i++)
        asm volatile("cp.async.cg.shared.global [%0], [%1], 16;"
                     :: "r"(d + i * 4096), "l"(s + i * 4096));
    asm volatile("cp.async.commit_group;" ::: "memory");
}
#define CPWG4() asm volatile("cp.async.wait_group 4;" ::: "memory")
#define CPWG3() asm volatile("cp.async.wait_group 3;" ::: "memory")
#define CPWG2() asm volatile("cp.async.wait_group 2;" ::: "memory")
#define CPWG1() asm volatile("cp.async.wait_group 1;" ::: "memory")
#define CPWG0() asm volatile("cp.async.wait_group 0;" ::: "memory")

// ---------------------------------------------------------------------------
// K1: blocks 0..31 : batch-0, 4 serial steps (emb | full-Wg0 u + scan |
//                    L2-GEMM h0 | L2-GEMM h1), all 5 loads issued at t=0.
//     blocks 32..46: chain b=1..15, 4 serial steps (emb | L0 | L1 | L2),
//                    full-layer (64KB) per step, ring-5 buffers. Writes g_v3.
// grid 47 x 256, dynamic smem 160KB (5 x 32KB)
// ---------------------------------------------------------------------------
__global__ void __launch_bounds__(256, 1)
k1(const float* __restrict__ z, const float* __restrict__ We,
   const float* __restrict__ be, const float* __restrict__ Wg,
   const float* __restrict__ bg) {
    extern __shared__ __align__(16) float buf[];   // 5 x 8192 floats
    __shared__ __align__(16) float gs[8][HD];
    __shared__ __align__(16) float hs[8][HD];
    __shared__ float zs[64];
    __shared__ float vv[HD];
    __shared__ float red[2][HD];
    __shared__ float ds[NN];
    int tid = threadIdx.x, bk = blockIdx.x;
    int d = tid & 127, hf = tid >> 7;
    int warp = tid >> 5, lane = tid & 31;
    uint32_t sb = (uint32_t)__cvta_generic_to_shared(buf);

    if (bk < 32) {
        // ---- batch-0: g0=We, g1=Wg0h0, g2=Wg0h1, g3=L2Wh0, g4=L2Wh1 ----
        const float* srcs[5] = { We, Wg, Wg + 64 * HD,
                                 Wg + HD * HD, Wg + HD * HD + 64 * HD };
#pragma unroll
        for (int i = 0; i < 5; i++) cp_stage(sb + i * 32768u, srcs[i], tid);
        if (tid < 64) zs[tid] = z[tid];
        ds[tid] = rsqrtf((float)(tid + 1));

        // step 0: embedding (needs g0)
        CPWG4(); __syncthreads();
        {
            const float* B = buf;
            float p0 = 0.f, p1 = 0.f; int kb = hf * 32;
#pragma unroll 8
            for (int kk = 0; kk < 32; kk += 2) {
                p0 = fmaf(zs[kb + kk],     B[(kb + kk) * HD + d],     p0);
                p1 = fmaf(zs[kb + kk + 1], B[(kb + kk + 1) * HD + d], p1);
            }
            red[hf][d] = p0 + p1;
        }
        __syncthreads();
        if (tid < 128) vv[d] = red[0][d] + red[1][d] + be[d];

        // step 1: u = vv @ Wg0 full (needs g1,g2), then closed-form L1 + scan
        CPWG2(); __syncthreads();
        {
            const float* B = buf + (hf ? 2 : 1) * 8192;
            int kb = hf * 64;
            float p0 = 0.f, p1 = 0.f;
#pragma unroll 8
            for (int kk = 0; kk < 64; kk += 2) {
                p0 = fmaf(vv[kb + kk],     B[kk * HD + d],       p0);
                p1 = fmaf(vv[kb + kk + 1], B[(kk + 1) * HD + d], p1);
            }
            red[hf][d] = p0 + p1;
        }
        __syncthreads();
        if (tid < 128) {
            float uf = red[0][d] + red[1][d];
            float bg0 = bg[d];
            float c = 0.f, Dex = 0.f;
            int base = bk * 8;
            for (int j = 0; j < base + 8; j++) {
                float dv = ds[j];
                float sc = fmaf(dv, Dex, dv * dv);
                float h1 = fmaxf(fmaf(sc, uf, bg0), 0.f);
                if (j >= base) gs[j - base][d] = fmaf(dv, c, dv * dv * h1);
                c = fmaf(dv, h1, c);
                Dex += dv;
            }
        }

        // steps 2-3: layer-2 GEMM halves (need g3 then g4)
        float4 acc = ((const float4*)(bg + HD))[lane];
        CPWG1(); __syncthreads();
        {
            const float4* Ws4 = (const float4*)(buf + 3 * 8192);
#pragma unroll 8
            for (int k = 0; k < 64; k++) {
                float g = gs[warp][k];
                float4 w = Ws4[k * 32 + lane];
                acc.x = fmaf(g, w.x, acc.x); acc.y = fmaf(g, w.y, acc.y);
                acc.z = fmaf(g, w.z, acc.z); acc.w = fmaf(g, w.w, acc.w);
            }
        }
        CPWG0(); __syncthreads();
        {
            const float4* Ws4 = (const float4*)(buf + 4 * 8192);
#pragma unroll 8
            for (int k = 0; k < 64; k++) {
                float g = gs[warp][64 + k];
                float4 w = Ws4[k * 32 + lane];
                acc.x = fmaf(g, w.x, acc.x); acc.y = fmaf(g, w.y, acc.y);
                acc.z = fmaf(g, w.z, acc.z); acc.w = fmaf(g, w.w, acc.w);
            }
        }
        acc.x = fmaxf(acc.x, 0.f); acc.y = fmaxf(acc.y, 0.f);
        acc.z = fmaxf(acc.z, 0.f); acc.w = fmaxf(acc.w, 0.f);
        int base = bk * 8;
        ((float4*)&g_h[base + warp][0])[lane] = acc;
        float dj = ds[base + warp];
        ((float4*)&hs[warp][0])[lane] = make_float4(acc.x * dj, acc.y * dj, acc.z * dj, acc.w * dj);
        __syncthreads();
        if (tid < HD) {
            float sum = 0.f;
#pragma unroll
            for (int w = 0; w < 8; w++) sum += hs[w][tid];
            g_P[bk][tid] = sum;
        }
    } else if (bk < 47) {
        // ---- chain b = bk-31: 4 steps, ring-5, groups g0..g6 ----
        int b = bk - 31;
        const float* srcs[7] = { We,
            Wg,               Wg + 64 * HD,
            Wg + HD * HD,     Wg + HD * HD + 64 * HD,
            Wg + 2 * HD * HD, Wg + 2 * HD * HD + 64 * HD };
#pragma unroll
        for (int i = 0; i < 5; i++) cp_stage(sb + i * 32768u, srcs[i], tid);
        if (tid < 64) zs[tid] = z[b * 64 + tid];

        // step 0: embedding (needs g0)
        CPWG4(); __syncthreads();
        {
            const float* B = buf;
            float p0 = 0.f, p1 = 0.f; int kb = hf * 32;
#pragma unroll 8
            for (int kk = 0; kk < 32; kk += 2) {
                p0 = fmaf(zs[kb + kk],     B[(kb + kk) * HD + d],     p0);
                p1 = fmaf(zs[kb + kk + 1], B[(kb + kk + 1) * HD + d], p1);
            }
            red[hf][d] = p0 + p1;
        }
        __syncthreads();
        if (tid < 128) vv[d] = red[0][d] + red[1][d] + be[d];
        cp_stage(sb, srcs[5], tid);   // g5: Wg2h0 -> buf0 (buf0 reads done)

        // step 1: layer 0 (needs g1,g2; pending g3,g4,g5 after wait)
        CPWG3(); __syncthreads();
        {
            const float* B = buf + (hf ? 2 : 1) * 8192;
            int kb = hf * 64;
            float p0 = 0.f, p1 = 0.f;
#pragma unroll 8
            for (int kk = 0; kk < 64; kk += 2) {
                p0 = fmaf(vv[kb + kk],     B[kk * HD + d],       p0);
                p1 = fmaf(vv[kb + kk + 1], B[(kk + 1) * HD + d], p1);
            }
            red[hf][d] = p0 + p1;
        }
        __syncthreads();
        if (tid < 128) vv[d] = fmaxf(red[0][d] + red[1][d] + bg[d], 0.f);
        cp_stage(sb + 32768u, srcs[6], tid);   // g6: Wg2h1 -> buf1

        // step 2: layer 1 (needs g3,g4; pending g5,g6 after wait)
        CPWG2(); __syncthreads();
        {
            const float* B = buf + (hf ? 4 : 3) * 8192;
            int kb = hf * 64;
            float p0 = 0.f, p1 = 0.f;
#pragma unroll 8
            for (int kk = 0; kk < 64; kk += 2) {
                p0 = fmaf(vv[kb + kk],     B[kk * HD + d],       p0);
                p1 = fmaf(vv[kb + kk + 1], B[(kk + 1) * HD + d], p1);
            }
            red[hf][d] = p0 + p1;
        }
        __syncthreads();
        if (tid < 128) vv[d] = fmaxf(red[0][d] + red[1][d] + bg[HD + d], 0.f);

        // step 3: layer 2 (needs g5,g6)
        CPWG0(); __syncthreads();
        {
            const float* B = buf + (hf ? 1 : 0) * 8192;
            int kb = hf * 64;
            float p0 = 0.f, p1 = 0.f;
#pragma unroll 8
            for (int kk = 0; kk < 64; kk += 2) {
                p0 = fmaf(vv[kb + kk],     B[kk * HD + d],       p0);
                p1 = fmaf(vv[kb + kk + 1], B[(kk + 1) * HD + d], p1);
            }
            red[hf][d] = p0 + p1;
        }
        __syncthreads();
        if (tid < 128)
            g_v3[b][d] = fmaxf(red[0][d] + red[1][d] + bg[2 * HD + d], 0.f);
    }
}

// ---------------------------------------------------------------------------
// K2: blocks 0..63 : scan -> layer-3 GEMM+relu -> W1a|W1b GEMM (4 stages).
//     blocks 64..78: chain logits for b=1..15 (v3 @ W1a/W1b -> sigmoid),
//                    2 serial steps, 4 loads up-front. Writes g_pb.
// grid 79 x 256, dynamic smem 128KB
// ---------------------------------------------------------------------------
__global__ void __launch_bounds__(256, 1)
k2(const float* __restrict__ Wg2, const float* __restrict__ bg2,
   const float* __restrict__ W1a, const float* __restrict__ W1b,
   const float* __restrict__ b1, const float* __restrict__ W2,
   const float* __restrict__ b2) {
    extern __shared__ __align__(16) float buf[];   // 4 x 8192 floats
    __shared__ __align__(16) float gs[8][HD];
    __shared__ __align__(16) float hs[8][HD];
    __shared__ float vv[HD];
    __shared__ float red[2][HD];
    __shared__ float wsum[8];
    int tid = threadIdx.x, blk = blockIdx.x;
    int d = tid & 127, hf = tid >> 7;
    int warp = tid >> 5, lane = tid & 31;
    uint32_t sb = (uint32_t)__cvta_generic_to_shared(buf);

    if (blk < 64) {
        int bk2 = blk >> 1, sel = blk & 1;
        int base = bk2 * 8;
        const float* WX = sel ? W1b : W1a;
        const float* srcs[4] = { Wg2, Wg2 + 64 * HD, WX, WX + 64 * HD };
#pragma unroll
        for (int i = 0; i < 4; i++) cp_stage(sb + i * 32768u, srcs[i], tid);

        // prologue: prefetched scan (overlaps in-flight loads)
        if (tid < 128) {
            float hr[8];
#pragma unroll
            for (int j = 0; j < 8; j++) hr[j] = g_h[base + j][tid];
            float ca[4] = {0.f, 0.f, 0.f, 0.f};
#pragma unroll
            for (int p = 0; p < 32; p++) {
                float v = g_P[p][tid];
                ca[p & 3] += (p < bk2) ? v : 0.f;
            }
            float c = (ca[0] + ca[1]) + (ca[2] + ca[3]);
#pragma unroll
            for (int j = 0; j < 8; j++) {
                float dv = rsqrtf((float)(base + j + 1));
                gs[j][tid] = fmaf(dv, c, dv * dv * hr[j]);
                c = fmaf(dv, hr[j], c);
            }
        }
        float4 acc = ((const float4*)bg2)[lane];
        float4 aX = sel ? make_float4(0.f, 0.f, 0.f, 0.f)
                        : ((const float4*)b1)[lane];
#pragma unroll
        for (int s = 0; s < 4; s++) {
            if (s == 0) { CPWG3(); } else if (s == 1) { CPWG2(); }
            else if (s == 2) { CPWG1(); } else { CPWG0(); }
            __syncthreads();
            const float4* Ws4 = (const float4*)(buf + s * 8192);
            const float* in = (s < 2) ? &gs[warp][0] : &hs[warp][0];
            int ko = (s & 1) * 64;
            float4 a = (s < 2) ? acc : aX;
#pragma unroll 8
            for (int k = 0; k < 64; k++) {
                float g = in[ko + k];
                float4 w = Ws4[k * 32 + lane];
                a.x = fmaf(g, w.x, a.x); a.y = fmaf(g, w.y, a.y);
                a.z = fmaf(g, w.z, a.z); a.w = fmaf(g, w.w, a.w);
            }
            if (s < 2) acc = a; else aX = a;
            if (s == 1) {   // h3 = relu(acc)
                acc.x = fmaxf(acc.x, 0.f); acc.y = fmaxf(acc.y, 0.f);
                acc.z = fmaxf(acc.z, 0.f); acc.w = fmaxf(acc.w, 0.f);
                ((float4*)&hs[warp][0])[lane] = acc;
            }
            __syncthreads();
        }
        if (sel) ((float4*)&g_B0[base + warp][0])[lane] = aX;
        else     ((float4*)&g_A0[base + warp][0])[lane] = aX;
    } else {
        // chain logit for b = blk-63
        int b = blk - 63;
        const float* srcs[4] = { W1a, W1a + 64 * HD, W1b, W1b + 64 * HD };
#pragma unroll
        for (int i = 0; i < 4; i++) cp_stage(sb + i * 32768u, srcs[i], tid);
        if (tid < 128) vv[d] = g_v3[b][d];

        float aAf = 0.f;
        // step A: W1a (needs g0,g1)
        CPWG2(); __syncthreads();
        {
            const float* B = buf + (hf ? 1 : 0) * 8192;
            int kb = hf * 64;
            float p0 = 0.f, p1 = 0.f;
#pragma unroll 8
            for (int kk = 0; kk < 64; kk += 2) {
                p0 = fmaf(vv[kb + kk],     B[kk * HD + d],       p0);
                p1 = fmaf(vv[kb + kk + 1], B[(kk + 1) * HD + d], p1);
            }
            red[hf][d] = p0 + p1;
        }
        __syncthreads();
        if (tid < 128) aAf = red[0][d] + red[1][d] + b1[d];

        // step B: W1b (needs g2,g3)
        CPWG0(); __syncthreads();
        {
            const float* B = buf + (hf ? 3 : 2) * 8192;
            int kb = hf * 64;
            float p0 = 0.f, p1 = 0.f;
#pragma unroll 8
            for (int kk = 0; kk < 64; kk += 2) {
                p0 = fmaf(vv[kb + kk],     B[kk * HD + d],       p0);
                p1 = fmaf(vv[kb + kk + 1], B[(kk + 1) * HD + d], p1);
            }
            red[hf][d] = p0 + p1;
        }
        __syncthreads();
        float t = 0.f;
        if (tid < 128) t = fmaxf(aAf + red[0][d] + red[1][d], 0.f) * W2[d];
        for (int off = 16; off > 0; off >>= 1)
            t += __shfl_down_sync(0xffffffffu, t, off);
        if ((tid & 31) == 0) wsum[tid >> 5] = t;
        __syncthreads();
        if (tid == 0) {
            float ssum = wsum[0] + wsum[1] + wsum[2] + wsum[3]
                       + wsum[4] + wsum[5] + wsum[6] + wsum[7] + b2[0];
            g_pb[b] = 1.f / (1.f + __expf(-ssum));
        }
    }
}

// ---------------------------------------------------------------------------
// K3: blocks 0..135 : batch-0 pairwise tiles (16x16, upper triangle, mirrored)
//     blocks 136..147: constant fill for b>=1 (320 rows each, diag 0)
// grid 148 x 256 (one wave)
// ---------------------------------------------------------------------------
__global__ void k3(const float* __restrict__ W2, const float* __restrict__ b2,
                   float* __restrict__ out) {
    int tid = threadIdx.x;
    int blk = blockIdx.x;
    if (blk < 136) {
        int ti = 0, rem = blk;
        while (rem >= 16 - ti) { rem -= 16 - ti; ti++; }
        int tj = ti + rem;

        __shared__ __align__(16) float a_sh[16][132];
        __shared__ __align__(16) float b_sh[16][132];
        __shared__ __align__(16) float w2s[HD];
        __shared__ float b2s;
        __shared__ float tile[16][17];
        for (int i = tid; i < 512; i += 256) {
            int r = i >> 5, d4 = i & 31;
            ((float4*)&a_sh[r][0])[d4] = ((const float4*)&g_A0[ti * 16 + r][0])[d4];
            ((float4*)&b_sh[r][0])[d4] = ((const float4*)&g_B0[tj * 16 + r][0])[d4];
        }
        if (tid < HD) w2s[tid] = W2[tid];
        if (tid == 0) b2s = b2[0];
        __syncthreads();

        int il = tid >> 4, jl = tid & 15;
        const float4* a4 = (const float4*)&a_sh[il][0];
        const float4* b4 = (const float4*)&b_sh[jl][0];
        const float4* w4 = (const float4*)w2s;
        float ac0 = 0.f, ac1 = 0.f, ac2 = 0.f, ac3 = 0.f;
#pragma unroll
        for (int qd = 0; qd < 8; qd++) {
            { float4 a=a4[qd],    b=b4[qd],    w=w4[qd];
              ac0 = fmaf(fmaxf(a.x+b.x,0.f),w.x,ac0); ac0 = fmaf(fmaxf(a.y+b.y,0.f),w.y,ac0);
              ac0 = fmaf(fmaxf(a.z+b.z,0.f),w.z,ac0); ac0 = fmaf(fmaxf(a.w+b.w,0.f),w.w,ac0); }
            { float4 a=a4[qd+8],  b=b4[qd+8],  w=w4[qd+8];
              ac1 = fmaf(fmaxf(a.x+b.x,0.f),w.x,ac1); ac1 = fmaf(fmaxf(a.y+b.y,0.f),w.y,ac1);
              ac1 = fmaf(fmaxf(a.z+b.z,0.f),w.z,ac1); ac1 = fmaf(fmaxf(a.w+b.w,0.f),w.w,ac1); }
            { float4 a=a4[qd+16], b=b4[qd+16], w=w4[qd+16];
              ac2 = fmaf(fmaxf(a.x+b.x,0.f),w.x,ac2); ac2 = fmaf(fmaxf(a.y+b.y,0.f),w.y,ac2);
              ac2 = fmaf(fmaxf(a.z+b.z,0.f),w.z,ac2); ac2 = fmaf(fmaxf(a.w+b.w,0.f),w.w,ac2); }
            { float4 a=a4[qd+24], b=b4[qd+24], w=w4[qd+24];
              ac3 = fmaf(fmaxf(a.x+b.x,0.f),w.x,ac3); ac3 = fmaf(fmaxf(a.y+b.y,0.f),w.y,ac3);
              ac3 = fmaf(fmaxf(a.z+b.z,0.f),w.z,ac3); ac3 = fmaf(fmaxf(a.w+b.w,0.f),w.w,ac3); }
        }
        float accv = (ac0 + ac1) + (ac2 + ac3);
        tile[il][jl] = 1.f / (1.f + __expf(-(accv + b2s)));
        __syncthreads();

        int r = tid >> 4, c = tid & 15;
        if (ti == tj) {
            float vo = (r < c) ? tile[r][c] : ((r > c) ? tile[c][r] : 0.f);
            out[((size_t)(ti * 16 + r)) * NN + ti * 16 + c] = vo;
        } else {
            out[((size_t)(ti * 16 + r)) * NN + tj * 16 + c] = tile[r][c];
            out[((size_t)(tj * 16 + r)) * NN + ti * 16 + c] = tile[c][r];
        }
    } else {
        __shared__ float pbs[NB];
        if (tid < NB) pbs[tid] = g_pb[tid];
        __syncthreads();
        int fid = blk - 136;
        int f4base = fid * 20480;          // 320 rows * 64 float4 per block
#pragma unroll 4
        for (int t = 0; t < 80; t++) {
            int idx = f4base + t * 256 + tid;
            int gr = idx >> 6;             // fill row 0..3839
            int c4 = idx & 63;
            int b = (gr >> 8) + 1;
            int i = gr & 255;
            float p = pbs[b];
            int j0 = c4 * 4;
            float4 vo;
            vo.x = (i == j0 + 0) ? 0.f : p;
            vo.y = (i == j0 + 1) ? 0.f : p;
            vo.z = (i == j0 + 2) ? 0.f : p;
            vo.w = (i == j0 + 3) ? 0.f : p;
            ((float4*)out)[((size_t)b * NN * NN + (size_t)i * NN) / 4 + c4] = vo;
        }
    }
}

// ---------------------------------------------------------------------------
extern "C" void kernel_launch(void* const* d_in, const int* in_sizes, int n_in,
                              void* d_out, int out_size) {
    const float* z   = (const float*)d_in[0];
    const float* We  = (const float*)d_in[1];
    const float* be  = (const float*)d_in[2];
    const float* Wg  = (const float*)d_in[3];
    const float* bg  = (const float*)d_in[4];
    const float* W1a = (const float*)d_in[5];
    const float* W1b = (const float*)d_in[6];
    const float* b1  = (const float*)d_in[7];
    const float* W2  = (const float*)d_in[8];
    const float* b2  = (const float*)d_in[9];
    float* out = (float*)d_out;

    cudaFuncSetAttribute(k1, cudaFuncAttributeMaxDynamicSharedMemorySize, 163840);
    cudaFuncSetAttribute(k2, cudaFuncAttributeMaxDynamicSharedMemorySize, 131072);

    k1<<<47, 256, 163840>>>(z, We, be, Wg, bg);
    k2<<<79, 256, 131072>>>(Wg + 2 * HD * HD, bg + 2 * HD, W1a, W1b, b1, W2, b2);
    k3<<<148, 256>>>(W2, b2, out);
}

// round 11
// speedup vs baseline: 1.1998x; 1.0614x over previous
#include <cuda_runtime.h>
#include <math.h>
#include <stdint.h>

#define HD 128
#define NN 256
#define NB 16

// Scratch (allocation-free rule: __device__ globals)
__device__ float g_h[NN][HD];    // layer-2 output (relu)
__device__ float g_P[32][HD];    // per-block partial sums of dinv*h (scan)
__device__ float g_v3[NB][HD];   // post-layer-3 vector per batch b>=1
__device__ float g_A0[NN][HD];   // h3 @ W1a + b1   (batch 0)
__device__ float g_B0[NN][HD];   // h3 @ W1b        (batch 0)
__device__ float g_pb[NB];       // constant edge prob per batch (b>=1)

// 32KB stage load via cp.async (8 x 16B per thread, 256 threads)
__device__ __forceinline__ void cp_stage(uint32_t dst, const float* src, int tid) {
    const char* s = (const char*)src + tid * 16;
    uint32_t d = dst + tid * 16;
#pragma unroll
    for (int i = 0; i < 8; i++)
        asm volatile("cp.async.cg.shared.global [%0], [%1], 16;"
                     :: "r"(d + i * 4096), "l"(s + i * 4096));
    asm volatile("cp.async.commit_group;" ::: "memory");
}
#define CPWG4() asm volatile("cp.async.wait_group 4;" ::: "memory")
#define CPWG3() asm volatile("cp.async.wait_group 3;" ::: "memory")
#define CPWG2() asm volatile("cp.async.wait_group 2;" ::: "memory")
#define CPWG1() asm volatile("cp.async.wait_group 1;" ::: "memory")
#define CPWG0() asm volatile("cp.async.wait_group 0;" ::: "memory")

// ---------------------------------------------------------------------------
// K1: blocks 0..31 : batch-0, 4 serial steps (emb | full-Wg0 u + scan |
//                    L2-GEMM h0 | L2-GEMM h1), all 5 loads issued at t=0.
//     blocks 32..46: chain b=1..15, 4 serial steps (emb | L0 | L1 | L2),
//                    full-layer (64KB) per step, ring-5 buffers. Writes g_v3.
// grid 47 x 256, dynamic smem 160KB (5 x 32KB)
// ---------------------------------------------------------------------------
__global__ void __launch_bounds__(256, 1)
k1(const float* __restrict__ z, const float* __restrict__ We,
   const float* __restrict__ be, const float* __restrict__ Wg,
   const float* __restrict__ bg) {
    extern __shared__ __align__(16) float buf[];   // 5 x 8192 floats
    __shared__ __align__(16) float gs[8][HD];
    __shared__ __align__(16) float hs[8][HD];
    __shared__ float zs[64];
    __shared__ float vv[HD];
    __shared__ float red[2][HD];
    __shared__ float ds[NN];
    int tid = threadIdx.x, bk = blockIdx.x;
    int d = tid & 127, hf = tid >> 7;
    int warp = tid >> 5, lane = tid & 31;
    uint32_t sb = (uint32_t)__cvta_generic_to_shared(buf);

    // let k2 launch + prefetch its weights while we run (PDL)
    cudaTriggerProgrammaticLaunchCompletion();

    if (bk < 32) {
        // ---- batch-0: g0=We, g1=Wg0h0, g2=Wg0h1, g3=L2Wh0, g4=L2Wh1 ----
        const float* srcs[5] = { We, Wg, Wg + 64 * HD,
                                 Wg + HD * HD, Wg + HD * HD + 64 * HD };
#pragma unroll
        for (int i = 0; i < 5; i++) cp_stage(sb + i * 32768u, srcs[i], tid);
        if (tid < 64) zs[tid] = z[tid];
        ds[tid] = rsqrtf((float)(tid + 1));

        // step 0: embedding (needs g0)
        CPWG4(); __syncthreads();
        {
            const float* B = buf;
            float p0 = 0.f, p1 = 0.f; int kb = hf * 32;
#pragma unroll 8
            for (int kk = 0; kk < 32; kk += 2) {
                p0 = fmaf(zs[kb + kk],     B[(kb + kk) * HD + d],     p0);
                p1 = fmaf(zs[kb + kk + 1], B[(kb + kk + 1) * HD + d], p1);
            }
            red[hf][d] = p0 + p1;
        }
        __syncthreads();
        if (tid < 128) vv[d] = red[0][d] + red[1][d] + be[d];

        // step 1: u = vv @ Wg0 full (needs g1,g2), then closed-form L1 + scan
        CPWG2(); __syncthreads();
        {
            const float* B = buf + (hf ? 2 : 1) * 8192;
            int kb = hf * 64;
            float p0 = 0.f, p1 = 0.f;
#pragma unroll 8
            for (int kk = 0; kk < 64; kk += 2) {
                p0 = fmaf(vv[kb + kk],     B[kk * HD + d],       p0);
                p1 = fmaf(vv[kb + kk + 1], B[(kk + 1) * HD + d], p1);
            }
            red[hf][d] = p0 + p1;
        }
        __syncthreads();
        if (tid < 128) {
            float uf = red[0][d] + red[1][d];
            float bg0 = bg[d];
            float c = 0.f, Dex = 0.f;
            int base = bk * 8;
            for (int j = 0; j < base + 8; j++) {
                float dv = ds[j];
                float sc = fmaf(dv, Dex, dv * dv);
                float h1 = fmaxf(fmaf(sc, uf, bg0), 0.f);
                if (j >= base) gs[j - base][d] = fmaf(dv, c, dv * dv * h1);
                c = fmaf(dv, h1, c);
                Dex += dv;
            }
        }

        // steps 2-3: layer-2 GEMM halves (need g3 then g4)
        float4 acc = ((const float4*)(bg + HD))[lane];
        CPWG1(); __syncthreads();
        {
            const float4* Ws4 = (const float4*)(buf + 3 * 8192);
#pragma unroll 8
            for (int k = 0; k < 64; k++) {
                float g = gs[warp][k];
                float4 w = Ws4[k * 32 + lane];
                acc.x = fmaf(g, w.x, acc.x); acc.y = fmaf(g, w.y, acc.y);
                acc.z = fmaf(g, w.z, acc.z); acc.w = fmaf(g, w.w, acc.w);
            }
        }
        CPWG0(); __syncthreads();
        {
            const float4* Ws4 = (const float4*)(buf + 4 * 8192);
#pragma unroll 8
            for (int k = 0; k < 64; k++) {
                float g = gs[warp][64 + k];
                float4 w = Ws4[k * 32 + lane];
                acc.x = fmaf(g, w.x, acc.x); acc.y = fmaf(g, w.y, acc.y);
                acc.z = fmaf(g, w.z, acc.z); acc.w = fmaf(g, w.w, acc.w);
            }
        }
        acc.x = fmaxf(acc.x, 0.f); acc.y = fmaxf(acc.y, 0.f);
        acc.z = fmaxf(acc.z, 0.f); acc.w = fmaxf(acc.w, 0.f);
        int base = bk * 8;
        ((float4*)&g_h[base + warp][0])[lane] = acc;
        float dj = ds[base + warp];
        ((float4*)&hs[warp][0])[lane] = make_float4(acc.x * dj, acc.y * dj, acc.z * dj, acc.w * dj);
        __syncthreads();
        if (tid < HD) {
            float sum = 0.f;
#pragma unroll
            for (int w = 0; w < 8; w++) sum += hs[w][tid];
            g_P[bk][tid] = sum;
        }
    } else if (bk < 47) {
        // ---- chain b = bk-31: 4 steps, ring-5, groups g0..g6 ----
        int b = bk - 31;
        const float* srcs[7] = { We,
            Wg,               Wg + 64 * HD,
            Wg + HD * HD,     Wg + HD * HD + 64 * HD,
            Wg + 2 * HD * HD, Wg + 2 * HD * HD + 64 * HD };
#pragma unroll
        for (int i = 0; i < 5; i++) cp_stage(sb + i * 32768u, srcs[i], tid);
        if (tid < 64) zs[tid] = z[b * 64 + tid];

        // step 0: embedding (needs g0)
        CPWG4(); __syncthreads();
        {
            const float* B = buf;
            float p0 = 0.f, p1 = 0.f; int kb = hf * 32;
#pragma unroll 8
            for (int kk = 0; kk < 32; kk += 2) {
                p0 = fmaf(zs[kb + kk],     B[(kb + kk) * HD + d],     p0);
                p1 = fmaf(zs[kb + kk + 1], B[(kb + kk + 1) * HD + d], p1);
            }
            red[hf][d] = p0 + p1;
        }
        __syncthreads();
        if (tid < 128) vv[d] = red[0][d] + red[1][d] + be[d];
        cp_stage(sb, srcs[5], tid);   // g5: Wg2h0 -> buf0 (buf0 reads done)

        // step 1: layer 0 (needs g1,g2; pending g3,g4,g5 after wait)
        CPWG3(); __syncthreads();
        {
            const float* B = buf + (hf ? 2 : 1) * 8192;
            int kb = hf * 64;
            float p0 = 0.f, p1 = 0.f;
#pragma unroll 8
            for (int kk = 0; kk < 64; kk += 2) {
                p0 = fmaf(vv[kb + kk],     B[kk * HD + d],       p0);
                p1 = fmaf(vv[kb + kk + 1], B[(kk + 1) * HD + d], p1);
            }
            red[hf][d] = p0 + p1;
        }
        __syncthreads();
        if (tid < 128) vv[d] = fmaxf(red[0][d] + red[1][d] + bg[d], 0.f);
        cp_stage(sb + 32768u, srcs[6], tid);   // g6: Wg2h1 -> buf1

        // step 2: layer 1 (needs g3,g4; pending g5,g6 after wait)
        CPWG2(); __syncthreads();
        {
            const float* B = buf + (hf ? 4 : 3) * 8192;
            int kb = hf * 64;
            float p0 = 0.f, p1 = 0.f;
#pragma unroll 8
            for (int kk = 0; kk < 64; kk += 2) {
                p0 = fmaf(vv[kb + kk],     B[kk * HD + d],       p0);
                p1 = fmaf(vv[kb + kk + 1], B[(kk + 1) * HD + d], p1);
            }
            red[hf][d] = p0 + p1;
        }
        __syncthreads();
        if (tid < 128) vv[d] = fmaxf(red[0][d] + red[1][d] + bg[HD + d], 0.f);

        // step 3: layer 2 (needs g5,g6)
        CPWG0(); __syncthreads();
        {
            const float* B = buf + (hf ? 1 : 0) * 8192;
            int kb = hf * 64;
            float p0 = 0.f, p1 = 0.f;
#pragma unroll 8
            for (int kk = 0; kk < 64; kk += 2) {
                p0 = fmaf(vv[kb + kk],     B[kk * HD + d],       p0);
                p1 = fmaf(vv[kb + kk + 1], B[(kk + 1) * HD + d], p1);
            }
            red[hf][d] = p0 + p1;
        }
        __syncthreads();
        if (tid < 128)
            g_v3[b][d] = fmaxf(red[0][d] + red[1][d] + bg[2 * HD + d], 0.f);
    }
}

// ---------------------------------------------------------------------------
// K2: blocks 0..63 : scan -> layer-3 GEMM+relu -> W1a|W1b GEMM (4 stages).
//     blocks 64..78: chain logits for b=1..15 (v3 @ W1a/W1b -> sigmoid).
// PDL: weight prefetch happens BEFORE the grid-dependency sync, concurrent
// with k1's tail. grid 79 x 256, dynamic smem 128KB
// ---------------------------------------------------------------------------
__global__ void __launch_bounds__(256, 1)
k2(const float* __restrict__ Wg2, const float* __restrict__ bg2,
   const float* __restrict__ W1a, const float* __restrict__ W1b,
   const float* __restrict__ b1, const float* __restrict__ W2,
   const float* __restrict__ b2) {
    extern __shared__ __align__(16) float buf[];   // 4 x 8192 floats
    __shared__ __align__(16) float gs[8][HD];
    __shared__ __align__(16) float hs[8][HD];
    __shared__ float vv[HD];
    __shared__ float red[2][HD];
    __shared__ float wsum[8];
    int tid = threadIdx.x, blk = blockIdx.x;
    int d = tid & 127, hf = tid >> 7;
    int warp = tid >> 5, lane = tid & 31;
    uint32_t sb = (uint32_t)__cvta_generic_to_shared(buf);

    // let k3 launch + stage its constants while we run (PDL)
    cudaTriggerProgrammaticLaunchCompletion();

    if (blk < 64) {
        int bk2 = blk >> 1, sel = blk & 1;
        int base = bk2 * 8;
        const float* WX = sel ? W1b : W1a;
        const float* srcs[4] = { Wg2, Wg2 + 64 * HD, WX, WX + 64 * HD };
#pragma unroll
        for (int i = 0; i < 4; i++) cp_stage(sb + i * 32768u, srcs[i], tid);

        // wait for k1's g_h / g_P to be visible (weights already in flight)
        cudaGridDependencySynchronize();

        // prologue: prefetched scan (overlaps in-flight loads)
        if (tid < 128) {
            float hr[8];
#pragma unroll
            for (int j = 0; j < 8; j++) hr[j] = g_h[base + j][tid];
            float ca[4] = {0.f, 0.f, 0.f, 0.f};
#pragma unroll
            for (int p = 0; p < 32; p++) {
                float v = g_P[p][tid];
                ca[p & 3] += (p < bk2) ? v : 0.f;
            }
            float c = (ca[0] + ca[1]) + (ca[2] + ca[3]);
#pragma unroll
            for (int j = 0; j < 8; j++) {
                float dv = rsqrtf((float)(base + j + 1));
                gs[j][tid] = fmaf(dv, c, dv * dv * hr[j]);
                c = fmaf(dv, hr[j], c);
            }
        }
        float4 acc = ((const float4*)bg2)[lane];
        float4 aX = sel ? make_float4(0.f, 0.f, 0.f, 0.f)
                        : ((const float4*)b1)[lane];
#pragma unroll
        for (int s = 0; s < 4; s++) {
            if (s == 0) { CPWG3(); } else if (s == 1) { CPWG2(); }
            else if (s == 2) { CPWG1(); } else { CPWG0(); }
            __syncthreads();
            const float4* Ws4 = (const float4*)(buf + s * 8192);
            const float* in = (s < 2) ? &gs[warp][0] : &hs[warp][0];
            int ko = (s & 1) * 64;
            float4 a = (s < 2) ? acc : aX;
#pragma unroll 8
            for (int k = 0; k < 64; k++) {
                float g = in[ko + k];
                float4 w = Ws4[k * 32 + lane];
                a.x = fmaf(g, w.x, a.x); a.y = fmaf(g, w.y, a.y);
                a.z = fmaf(g, w.z, a.z); a.w = fmaf(g, w.w, a.w);
            }
            if (s < 2) acc = a; else aX = a;
            if (s == 1) {   // h3 = relu(acc)
                acc.x = fmaxf(acc.x, 0.f); acc.y = fmaxf(acc.y, 0.f);
                acc.z = fmaxf(acc.z, 0.f); acc.w = fmaxf(acc.w, 0.f);
                ((float4*)&hs[warp][0])[lane] = acc;
            }
            __syncthreads();
        }
        if (sel) ((float4*)&g_B0[base + warp][0])[lane] = aX;
        else     ((float4*)&g_A0[base + warp][0])[lane] = aX;
    } else {
        // chain logit for b = blk-63
        int b = blk - 63;
        const float* srcs[4] = { W1a, W1a + 64 * HD, W1b, W1b + 64 * HD };
#pragma unroll
        for (int i = 0; i < 4; i++) cp_stage(sb + i * 32768u, srcs[i], tid);

        cudaGridDependencySynchronize();   // need g_v3 from k1
        if (tid < 128) vv[d] = g_v3[b][d];

        float aAf = 0.f;
        // step A: W1a (needs g0,g1)
        CPWG2(); __syncthreads();
        {
            const float* B = buf + (hf ? 1 : 0) * 8192;
            int kb = hf * 64;
            float p0 = 0.f, p1 = 0.f;
#pragma unroll 8
            for (int kk = 0; kk < 64; kk += 2) {
                p0 = fmaf(vv[kb + kk],     B[kk * HD + d],       p0);
                p1 = fmaf(vv[kb + kk + 1], B[(kk + 1) * HD + d], p1);
            }
            red[hf][d] = p0 + p1;
        }
        __syncthreads();
        if (tid < 128) aAf = red[0][d] + red[1][d] + b1[d];

        // step B: W1b (needs g2,g3)
        CPWG0(); __syncthreads();
        {
            const float* B = buf + (hf ? 3 : 2) * 8192;
            int kb = hf * 64;
            float p0 = 0.f, p1 = 0.f;
#pragma unroll 8
            for (int kk = 0; kk < 64; kk += 2) {
                p0 = fmaf(vv[kb + kk],     B[kk * HD + d],       p0);
                p1 = fmaf(vv[kb + kk + 1], B[(kk + 1) * HD + d], p1);
            }
            red[hf][d] = p0 + p1;
        }
        __syncthreads();
        float t = 0.f;
        if (tid < 128) t = fmaxf(aAf + red[0][d] + red[1][d], 0.f) * W2[d];
        for (int off = 16; off > 0; off >>= 1)
            t += __shfl_down_sync(0xffffffffu, t, off);
        if ((tid & 31) == 0) wsum[tid >> 5] = t;
        __syncthreads();
        if (tid == 0) {
            float ssum = wsum[0] + wsum[1] + wsum[2] + wsum[3]
                       + wsum[4] + wsum[5] + wsum[6] + wsum[7] + b2[0];
            g_pb[b] = 1.f / (1.f + __expf(-ssum));
        }
    }
}

// ---------------------------------------------------------------------------
// K3: blocks 0..135 : batch-0 pairwise tiles (16x16, upper triangle, mirrored)
//     blocks 136..147: constant fill for b>=1 (320 rows each, diag 0)
// PDL: W2/b2 staged before the grid-dependency sync. grid 148 x 256
// ---------------------------------------------------------------------------
__global__ void k3(const float* __restrict__ W2, const float* __restrict__ b2,
                   float* __restrict__ out) {
    int tid = threadIdx.x;
    int blk = blockIdx.x;
    if (blk < 136) {
        int ti = 0, rem = blk;
        while (rem >= 16 - ti) { rem -= 16 - ti; ti++; }
        int tj = ti + rem;

        __shared__ __align__(16) float a_sh[16][132];
        __shared__ __align__(16) float b_sh[16][132];
        __shared__ __align__(16) float w2s[HD];
        __shared__ float b2s;
        __shared__ float tile[16][17];
        // stage inputs that don't depend on k2 BEFORE the dependency sync
        if (tid < HD) w2s[tid] = W2[tid];
        if (tid == 0) b2s = b2[0];

        cudaGridDependencySynchronize();   // need g_A0 / g_B0 from k2

        for (int i = tid; i < 512; i += 256) {
            int r = i >> 5, d4 = i & 31;
            ((float4*)&a_sh[r][0])[d4] = ((const float4*)&g_A0[ti * 16 + r][0])[d4];
            ((float4*)&b_sh[r][0])[d4] = ((const float4*)&g_B0[tj * 16 + r][0])[d4];
        }
        __syncthreads();

        int il = tid >> 4, jl = tid & 15;
        const float4* a4 = (const float4*)&a_sh[il][0];
        const float4* b4 = (const float4*)&b_sh[jl][0];
        const float4* w4 = (const float4*)w2s;
        float ac0 = 0.f, ac1 = 0.f, ac2 = 0.f, ac3 = 0.f;
#pragma unroll
        for (int qd = 0; qd < 8; qd++) {
            { float4 a=a4[qd],    b=b4[qd],    w=w4[qd];
              ac0 = fmaf(fmaxf(a.x+b.x,0.f),w.x,ac0); ac0 = fmaf(fmaxf(a.y+b.y,0.f),w.y,ac0);
              ac0 = fmaf(fmaxf(a.z+b.z,0.f),w.z,ac0); ac0 = fmaf(fmaxf(a.w+b.w,0.f),w.w,ac0); }
            { float4 a=a4[qd+8],  b=b4[qd+8],  w=w4[qd+8];
              ac1 = fmaf(fmaxf(a.x+b.x,0.f),w.x,ac1); ac1 = fmaf(fmaxf(a.y+b.y,0.f),w.y,ac1);
              ac1 = fmaf(fmaxf(a.z+b.z,0.f),w.z,ac1); ac1 = fmaf(fmaxf(a.w+b.w,0.f),w.w,ac1); }
            { float4 a=a4[qd+16], b=b4[qd+16], w=w4[qd+16];
              ac2 = fmaf(fmaxf(a.x+b.x,0.f),w.x,ac2); ac2 = fmaf(fmaxf(a.y+b.y,0.f),w.y,ac2);
              ac2 = fmaf(fmaxf(a.z+b.z,0.f),w.z,ac2); ac2 = fmaf(fmaxf(a.w+b.w,0.f),w.w,ac2); }
            { float4 a=a4[qd+24], b=b4[qd+24], w=w4[qd+24];
              ac3 = fmaf(fmaxf(a.x+b.x,0.f),w.x,ac3); ac3 = fmaf(fmaxf(a.y+b.y,0.f),w.y,ac3);
              ac3 = fmaf(fmaxf(a.z+b.z,0.f),w.z,ac3); ac3 = fmaf(fmaxf(a.w+b.w,0.f),w.w,ac3); }
        }
        float accv = (ac0 + ac1) + (ac2 + ac3);
        tile[il][jl] = 1.f / (1.f + __expf(-(accv + b2s)));
        __syncthreads();

        int r = tid >> 4, c = tid & 15;
        if (ti == tj) {
            float vo = (r < c) ? tile[r][c] : ((r > c) ? tile[c][r] : 0.f);
            out[((size_t)(ti * 16 + r)) * NN + ti * 16 + c] = vo;
        } else {
            out[((size_t)(ti * 16 + r)) * NN + tj * 16 + c] = tile[r][c];
            out[((size_t)(tj * 16 + r)) * NN + ti * 16 + c] = tile[c][r];
        }
    } else {
        __shared__ float pbs[NB];
        cudaGridDependencySynchronize();   // need g_pb from k2
        if (tid < NB) pbs[tid] = g_pb[tid];
        __syncthreads();
        int fid = blk - 136;
        int f4base = fid * 20480;          // 320 rows * 64 float4 per block
#pragma unroll 4
        for (int t = 0; t < 80; t++) {
            int idx = f4base + t * 256 + tid;
            int gr = idx >> 6;             // fill row 0..3839
            int c4 = idx & 63;
            int b = (gr >> 8) + 1;
            int i = gr & 255;
            float p = pbs[b];
            int j0 = c4 * 4;
            float4 vo;
            vo.x = (i == j0 + 0) ? 0.f : p;
            vo.y = (i == j0 + 1) ? 0.f : p;
            vo.z = (i == j0 + 2) ? 0.f : p;
            vo.w = (i == j0 + 3) ? 0.f : p;
            ((float4*)out)[((size_t)b * NN * NN + (size_t)i * NN) / 4 + c4] = vo;
        }
    }
}

// ---------------------------------------------------------------------------
extern "C" void kernel_launch(void* const* d_in, const int* in_sizes, int n_in,
                              void* d_out, int out_size) {
    const float* z   = (const float*)d_in[0];
    const float* We  = (const float*)d_in[1];
    const float* be  = (const float*)d_in[2];
    const float* Wg  = (const float*)d_in[3];
    const float* bg  = (const float*)d_in[4];
    const float* W1a = (const float*)d_in[5];
    const float* W1b = (const float*)d_in[6];
    const float* b1  = (const float*)d_in[7];
    const float* W2  = (const float*)d_in[8];
    const float* b2  = (const float*)d_in[9];
    float* out = (float*)d_out;

    cudaFuncSetAttribute(k1, cudaFuncAttributeMaxDynamicSharedMemorySize, 163840);
    cudaFuncSetAttribute(k2, cudaFuncAttributeMaxDynamicSharedMemorySize, 131072);

    // k1: normal launch
    k1<<<47, 256, 163840>>>(z, We, be, Wg, bg);

    // k2, k3: programmatic dependent launches (overlap launch + prefetch
    // with predecessor execution; gridDependencySynchronize guards data)
    cudaLaunchAttribute attrs[1];
    attrs[0].id = cudaLaunchAttributeProgrammaticStreamSerialization;
    attrs[0].val.programmaticStreamSerializationAllowed = 1;

    {
        cudaLaunchConfig_t cfg = {};
        cfg.gridDim = dim3(79);
        cfg.blockDim = dim3(256);
        cfg.dynamicSmemBytes = 131072;
        cfg.stream = 0;
        cfg.attrs = attrs;
        cfg.numAttrs = 1;
        cudaLaunchKernelEx(&cfg, k2, Wg + 2 * HD * HD, bg + 2 * HD,
                           W1a, W1b, b1, W2, b2);
    }
    {
        cudaLaunchConfig_t cfg = {};
        cfg.gridDim = dim3(148);
        cfg.blockDim = dim3(256);
        cfg.dynamicSmemBytes = 0;
        cfg.stream = 0;
        cfg.attrs = attrs;
        cfg.numAttrs = 1;
        cudaLaunchKernelEx(&cfg, k3, W2, b2, out);
    }
}